// round 14
// baseline (speedup 1.0000x reference)
#include <cuda_runtime.h>
#include <cuda_fp16.h>
#include <cstdint>

#define B_   4
#define L_   1024
#define D_   1024
#define H_   16
#define HD_  64
#define M_TOT (B_ * L_)   // 4096

// Scratch (static device globals — allocation-guard safe)
__device__ __half g_Iqh[M_TOT * D_], g_Iql[M_TOT * D_];   // query input split (2-term)
__device__ __half g_Ikh[M_TOT * D_];                      // key input (1-term)
__device__ __half g_Ivh[M_TOT * D_];                      // value input (1-term)
__device__ __half g_Wq16[D_ * D_], g_Wk16[D_ * D_], g_Wv16[D_ * D_], g_Wo16[D_ * D_];
__device__ __half g_Qhi[M_TOT * D_];                      // Q projected (fp16, pre-scaled 0.125*log2e)
__device__ __half g_Khi[M_TOT * D_], g_Vhi[M_TOT * D_];
__device__ __half g_Athi[M_TOT * D_];                     // attention out (fp16)

// ===========================================================================
// Helpers
// ===========================================================================
__device__ __forceinline__ uint32_t smem_u32(const void* p) {
    uint32_t a;
    asm("{ .reg .u64 t; cvta.to.shared.u64 t, %1; cvt.u32.u64 %0, t; }" : "=r"(a) : "l"(p));
    return a;
}
__device__ __forceinline__ void ldsm_x4(uint32_t& r0, uint32_t& r1, uint32_t& r2, uint32_t& r3, uint32_t a) {
    asm volatile("ldmatrix.sync.aligned.m8n8.x4.shared.b16 {%0,%1,%2,%3}, [%4];"
                 : "=r"(r0), "=r"(r1), "=r"(r2), "=r"(r3) : "r"(a));
}
__device__ __forceinline__ void ldsm_x2t(uint32_t& r0, uint32_t& r1, uint32_t a) {
    asm volatile("ldmatrix.sync.aligned.m8n8.x2.trans.shared.b16 {%0,%1}, [%2];"
                 : "=r"(r0), "=r"(r1) : "r"(a));
}
__device__ __forceinline__ void mma_f16(float* c,
    uint32_t a0, uint32_t a1, uint32_t a2, uint32_t a3, uint32_t b0, uint32_t b1) {
    asm volatile("mma.sync.aligned.m16n8k16.row.col.f32.f16.f16.f32 "
                 "{%0,%1,%2,%3}, {%4,%5,%6,%7}, {%8,%9}, {%0,%1,%2,%3};"
                 : "+f"(c[0]), "+f"(c[1]), "+f"(c[2]), "+f"(c[3])
                 : "r"(a0), "r"(a1), "r"(a2), "r"(a3), "r"(b0), "r"(b1));
}
__device__ __forceinline__ uint32_t pack_h(__half lo, __half hi) {
    return ((uint32_t)__half_as_ushort(hi) << 16) | __half_as_ushort(lo);
}
__device__ __forceinline__ void split2h(float x, __half& h, __half& l) {
    h = __float2half_rn(x);
    l = __float2half_rn(x - __half2float(h));
}
__device__ __forceinline__ void cp16(uint32_t dst, const void* src) {
    asm volatile("cp.async.cg.shared.global [%0], [%1], 16;" :: "r"(dst), "l"(src));
}
__device__ __forceinline__ void cp_commit() { asm volatile("cp.async.commit_group;"); }
template<int N> __device__ __forceinline__ void cp_wait() {
    asm volatile("cp.async.wait_group %0;" :: "n"(N));
}

// ===========================================================================
// Prep: query -> hi/lo split; key/value/weights -> single fp16.  grid (512,1,7)
// ===========================================================================
__global__ __launch_bounds__(256) void prep_kernel(
    const float* __restrict__ q, const float* __restrict__ k, const float* __restrict__ v,
    const float* __restrict__ wq, const float* __restrict__ wk,
    const float* __restrict__ wv, const float* __restrict__ wo,
    __half* qh, __half* ql, __half* kh, __half* vh,
    __half* wqh, __half* wkh, __half* wvh, __half* woh)
{
    const int z = blockIdx.z;
    const int base = blockIdx.x * 256 + threadIdx.x;
    if (z == 0) {
        #pragma unroll
        for (int i = 0; i < 8; i++) {
            int e4 = base + i * 131072;
            float4 x = reinterpret_cast<const float4*>(q)[e4];
            __half h0, h1, h2, h3, l0, l1, l2, l3;
            split2h(x.x, h0, l0); split2h(x.y, h1, l1);
            split2h(x.z, h2, l2); split2h(x.w, h3, l3);
            uint2 hv = { pack_h(h0, h1), pack_h(h2, h3) };
            uint2 lv = { pack_h(l0, l1), pack_h(l2, l3) };
            *reinterpret_cast<uint2*>(qh + (size_t)e4 * 4) = hv;
            *reinterpret_cast<uint2*>(ql + (size_t)e4 * 4) = lv;
        }
    } else if (z < 3) {
        const float* src = (z == 1) ? k : v;
        __half* dst = (z == 1) ? kh : vh;
        #pragma unroll
        for (int i = 0; i < 8; i++) {
            int e4 = base + i * 131072;
            float4 x = reinterpret_cast<const float4*>(src)[e4];
            uint2 hv = { pack_h(__float2half_rn(x.x), __float2half_rn(x.y)),
                         pack_h(__float2half_rn(x.z), __float2half_rn(x.w)) };
            *reinterpret_cast<uint2*>(dst + (size_t)e4 * 4) = hv;
        }
    } else {
        const float* src = (z == 3) ? wq : (z == 4) ? wk : (z == 5) ? wv : wo;
        __half* dst = (z == 3) ? wqh : (z == 4) ? wkh : (z == 5) ? wvh : woh;
        #pragma unroll
        for (int i = 0; i < 2; i++) {
            int e4 = base + i * 131072;
            float4 x = reinterpret_cast<const float4*>(src)[e4];
            uint2 wv2 = { pack_h(__float2half_rn(x.x), __float2half_rn(x.y)),
                          pack_h(__float2half_rn(x.z), __float2half_rn(x.w)) };
            *reinterpret_cast<uint2*>(dst + (size_t)e4 * 4) = wv2;
        }
    }
}

// ===========================================================================
// fp16 HMMA GEMM, 3-stage cp.async pipeline, ONE barrier per chunk.
//   C = (Ah [+ Al]) @ Wh^T + bias, then * oscale.
// ===========================================================================
#define BKC   32
#define NCH   (D_ / BKC)   // 32
#define SST   40
#define ARR_H (128 * SST)
#define STG_H (3 * ARR_H)
#define GSMEM (3 * STG_H * 2)          // 92160 bytes (3 stages)

struct GemmArgs {
    const __half* Ah;
    const __half* Al;
    const __half* Wh;
    const float*  bias;
    float*  C;
    __half* Chi;
    __half* Clo;
    int     two_term;
    float   oscale;
};

__device__ __forceinline__ void issue_chunk(
    const GemmArgs& g, int m0, int n0, int k0, int t, uint32_t stage_b)
{
    #pragma unroll
    for (int i = 0; i < 2; i++) {
        int s  = t + (i << 8);
        int r  = s >> 2;
        int c8 = (s & 3) << 3;
        uint32_t d = stage_b + (uint32_t)(r * SST + c8) * 2;
        size_t goff = (size_t)(m0 + r) * D_ + k0 + c8;
        cp16(d, g.Ah + goff);
        if (g.two_term) cp16(d + ARR_H * 2, g.Al + goff);
        cp16(d + 2 * ARR_H * 2, g.Wh + (size_t)(n0 + r) * D_ + k0 + c8);
    }
    cp_commit();
}

__global__ __launch_bounds__(256, 2) void gemm_f16_multi(
    GemmArgs ga0, GemmArgs ga1, GemmArgs ga2)
{
    extern __shared__ __half dsm[];
    const GemmArgs g = (blockIdx.z == 0) ? ga0 : ((blockIdx.z == 1) ? ga1 : ga2);

    const int t    = threadIdx.x;
    const int lane = t & 31;
    const int warp = t >> 5;
    const int wm   = warp >> 2;
    const int wn   = warp & 3;
    const int m0   = blockIdx.y * 128;
    const int n0   = blockIdx.x * 128;
    const uint32_t sb = smem_u32(dsm);

    float acc[4][4][4];
    #pragma unroll
    for (int i = 0; i < 4; i++)
        #pragma unroll
        for (int j = 0; j < 4; j++)
            #pragma unroll
            for (int r = 0; r < 4; r++) acc[i][j][r] = 0.0f;

    issue_chunk(g, m0, n0, 0,   t, sb);
    issue_chunk(g, m0, n0, BKC, t, sb + STG_H * 2);

    for (int ck = 0; ck < NCH; ck++) {
        const int st = ck % 3;
        const __half* cah = dsm + st * STG_H;
        const __half* cal = cah + ARR_H;
        const __half* cbh = cah + 2 * ARR_H;

        if (ck + 1 < NCH) cp_wait<1>(); else cp_wait<0>();
        __syncthreads();     // single barrier: orders reads of stage (ck+2)%3 (done at ck-1)
        if (ck + 2 < NCH)
            issue_chunk(g, m0, n0, (ck + 2) * BKC, t, sb + ((ck + 2) % 3) * STG_H * 2);

        #pragma unroll
        for (int ks = 0; ks < 2; ks++) {
            const int k0 = ks * 16;
            uint32_t bh[4][2];
            #pragma unroll
            for (int jp = 0; jp < 2; jp++) {   // x4: lanes 16-31 fetch the second n-group
                int row = wn * 32 + (jp * 2 + (lane >> 4)) * 8 + (lane & 7);
                int col = k0 + (((lane >> 3) & 1) << 3);
                ldsm_x4(bh[jp * 2][0], bh[jp * 2][1], bh[jp * 2 + 1][0], bh[jp * 2 + 1][1],
                        smem_u32(cbh + row * SST + col));
            }
            #pragma unroll
            for (int i = 0; i < 4; i++) {
                int row = wm * 64 + i * 16 + (lane & 15);
                int col = k0 + ((lane >> 4) << 3);
                uint32_t ah0, ah1, ah2, ah3;
                ldsm_x4(ah0, ah1, ah2, ah3, smem_u32(cah + row * SST + col));
                #pragma unroll
                for (int j = 0; j < 4; j++)
                    mma_f16(acc[i][j], ah0, ah1, ah2, ah3, bh[j][0], bh[j][1]);
                if (g.two_term) {
                    uint32_t al0, al1, al2, al3;
                    ldsm_x4(al0, al1, al2, al3, smem_u32(cal + row * SST + col));
                    #pragma unroll
                    for (int j = 0; j < 4; j++)
                        mma_f16(acc[i][j], al0, al1, al2, al3, bh[j][0], bh[j][1]);
                }
            }
        }
    }

    const int lr = lane >> 2;
    const int lc = (lane & 3) << 1;
    #pragma unroll
    for (int i = 0; i < 4; i++) {
        #pragma unroll
        for (int j = 0; j < 4; j++) {
            int row = m0 + wm * 64 + i * 16 + lr;
            int col = n0 + wn * 32 + j * 8 + lc;
            float2 bz = *reinterpret_cast<const float2*>(g.bias + col);
            float v0 = (acc[i][j][0] + bz.x) * g.oscale;
            float v1 = (acc[i][j][1] + bz.y) * g.oscale;
            float v2 = (acc[i][j][2] + bz.x) * g.oscale;
            float v3 = (acc[i][j][3] + bz.y) * g.oscale;
            if (g.Chi) {
                if (g.Clo) {
                    __half h0, h1, h2, h3, l0, l1, l2, l3;
                    split2h(v0, h0, l0); split2h(v1, h1, l1);
                    split2h(v2, h2, l2); split2h(v3, h3, l3);
                    *reinterpret_cast<uint32_t*>(g.Chi + (size_t)row * D_ + col)       = pack_h(h0, h1);
                    *reinterpret_cast<uint32_t*>(g.Clo + (size_t)row * D_ + col)       = pack_h(l0, l1);
                    *reinterpret_cast<uint32_t*>(g.Chi + (size_t)(row + 8) * D_ + col) = pack_h(h2, h3);
                    *reinterpret_cast<uint32_t*>(g.Clo + (size_t)(row + 8) * D_ + col) = pack_h(l2, l3);
                } else {
                    *reinterpret_cast<uint32_t*>(g.Chi + (size_t)row * D_ + col) =
                        pack_h(__float2half_rn(v0), __float2half_rn(v1));
                    *reinterpret_cast<uint32_t*>(g.Chi + (size_t)(row + 8) * D_ + col) =
                        pack_h(__float2half_rn(v2), __float2half_rn(v3));
                }
            } else {
                float2 o0 = { v0, v1 }, o1 = { v2, v3 };
                *reinterpret_cast<float2*>(g.C + (size_t)row * D_ + col) = o0;
                *reinterpret_cast<float2*>(g.C + (size_t)(row + 8) * D_ + col) = o1;
            }
        }
    }
}

// ===========================================================================
// HMMA flash attention: 3-stage cp.async K/V pipeline, one barrier per tile.
// Q pre-scaled by 0.125*log2e -> softmax in exp2 domain.
// ===========================================================================
#define FST   72
#define FSTG  (64 * FST)                       // halves per stage array
#define FSMEM (6 * FSTG * 2 + 3 * 64 * 4)      // KHx3 + VHx3 + MIx3 = 56832 B

__global__ __launch_bounds__(256) void flash_hmma_kernel(
    const __half* __restrict__ Qhi,
    const __half* __restrict__ Khi, const __half* __restrict__ Vhi,
    const int* __restrict__ mask,
    __half* __restrict__ Oh)
{
    extern __shared__ __half fsm[];
    __half* KHs = fsm;                 // [3][64][FST]
    __half* VHs = fsm + 3 * FSTG;      // [3][64][FST]
    int*    MIs = (int*)(fsm + 6 * FSTG);   // [3][64]

    const int t    = threadIdx.x;
    const int lane = t & 31;
    const int warp = t >> 5;
    const int qt   = blockIdx.x;
    const int h    = blockIdx.y;
    const int b    = blockIdx.z;
    const int grow0 = b * L_ + qt * 128;
    const int ghc   = h * HD_;

    // ---- stage Q tile (128 rows, hi only) through stage-0 arrays ----
    #pragma unroll
    for (int i = 0; i < 2; i++) {
        int v = t + i * 256;
        int r = v >> 2;
        int c = (v & 3) << 4;
        __half* dh = (r < 64) ? (KHs + r * FST + c) : (VHs + (r - 64) * FST + c);
        *reinterpret_cast<uint4*>(dh) =
            *reinterpret_cast<const uint4*>(Qhi + (size_t)(grow0 + r) * D_ + ghc + c);
        *reinterpret_cast<uint4*>(dh + 8) =
            *reinterpret_cast<const uint4*>(Qhi + (size_t)(grow0 + r) * D_ + ghc + c + 8);
    }
    __syncthreads();

    uint32_t qh[4][4];
    {
        int ar = warp * 16 + (lane & 15);
        int ac = (lane >> 4) << 3;
        const __half* sh = (ar < 64) ? (KHs + ar * FST) : (VHs + (ar - 64) * FST);
        #pragma unroll
        for (int kc = 0; kc < 4; kc++)
            ldsm_x4(qh[kc][0], qh[kc][1], qh[kc][2], qh[kc][3], smem_u32(sh + kc * 16 + ac));
    }
    __syncthreads();   // Q fragments read; stages free for K/V

    float O[8][4];
    #pragma unroll
    for (int j = 0; j < 8; j++)
        #pragma unroll
        for (int r = 0; r < 4; r++) O[j][r] = 0.0f;
    float m0 = -1e30f, m1 = -1e30f, l0 = 0.0f, l1 = 0.0f;

    auto issue_kv = [&](int tile, int st) {
        const int krow0 = b * L_ + tile * 64;
        __half* kb = KHs + st * FSTG;
        __half* vb = VHs + st * FSTG;
        #pragma unroll
        for (int i = 0; i < 2; i++) {
            int s = t + i * 256;
            int r = s >> 3;
            int c = (s & 7) << 3;
            size_t gb = (size_t)(krow0 + r) * D_ + ghc + c;
            cp16(smem_u32(kb + r * FST + c), Khi + gb);
            cp16(smem_u32(vb + r * FST + c), Vhi + gb);
        }
        if (t < 16) cp16(smem_u32(MIs + st * 64 + t * 4), mask + b * L_ + tile * 64 + t * 4);
        cp_commit();
    };

    issue_kv(0, 0);
    issue_kv(1, 1);

    for (int kt = 0; kt < 16; kt++) {
        const int st = kt % 3;
        const __half* kb = KHs + st * FSTG;
        const __half* vb = VHs + st * FSTG;
        const int*    mi = MIs + st * 64;

        if (kt + 1 < 16) cp_wait<1>(); else cp_wait<0>();
        __syncthreads();   // single barrier; stage (kt+2)%3 readers finished at kt-1
        if (kt + 2 < 16) issue_kv(kt + 2, (kt + 2) % 3);

        // ---- S = Q K^T (single term, Q pre-scaled incl. log2e) ----
        float S[8][4];
        #pragma unroll
        for (int j = 0; j < 8; j++)
            S[j][0] = S[j][1] = S[j][2] = S[j][3] = 0.0f;
        #pragma unroll
        for (int jp = 0; jp < 4; jp++) {       // x4 over n-group pairs
            int j0 = jp * 2;
            int brow = (j0 + (lane >> 4)) * 8 + (lane & 7);
            #pragma unroll
            for (int kc = 0; kc < 4; kc++) {
                int bcol = kc * 16 + (((lane >> 3) & 1) << 3);
                uint32_t b0, b1, b2, b3;
                ldsm_x4(b0, b1, b2, b3, smem_u32(kb + brow * FST + bcol));
                mma_f16(S[j0],     qh[kc][0], qh[kc][1], qh[kc][2], qh[kc][3], b0, b1);
                mma_f16(S[j0 + 1], qh[kc][0], qh[kc][1], qh[kc][2], qh[kc][3], b2, b3);
            }
        }

        // ---- softmax in exp2 domain ----
        float rmax0 = -3.0e38f, rmax1 = -3.0e38f;
        #pragma unroll
        for (int j = 0; j < 8; j++) {
            int cidx = j * 8 + ((lane & 3) << 1);
            float ma = mi[cidx]     ? -1e30f : 0.0f;
            float mb = mi[cidx + 1] ? -1e30f : 0.0f;
            S[j][0] += ma; S[j][1] += mb; S[j][2] += ma; S[j][3] += mb;
            rmax0 = fmaxf(rmax0, fmaxf(S[j][0], S[j][1]));
            rmax1 = fmaxf(rmax1, fmaxf(S[j][2], S[j][3]));
        }
        rmax0 = fmaxf(rmax0, __shfl_xor_sync(0xffffffffu, rmax0, 1));
        rmax0 = fmaxf(rmax0, __shfl_xor_sync(0xffffffffu, rmax0, 2));
        rmax1 = fmaxf(rmax1, __shfl_xor_sync(0xffffffffu, rmax1, 1));
        rmax1 = fmaxf(rmax1, __shfl_xor_sync(0xffffffffu, rmax1, 2));

        float mn0 = fmaxf(m0, rmax0), mn1 = fmaxf(m1, rmax1);
        float a0 = exp2f(m0 - mn0), a1 = exp2f(m1 - mn1);
        m0 = mn0; m1 = mn1;

        float sum0 = 0.0f, sum1 = 0.0f;
        #pragma unroll
        for (int j = 0; j < 8; j++) {
            S[j][0] = exp2f(S[j][0] - mn0); sum0 += S[j][0];
            S[j][1] = exp2f(S[j][1] - mn0); sum0 += S[j][1];
            S[j][2] = exp2f(S[j][2] - mn1); sum1 += S[j][2];
            S[j][3] = exp2f(S[j][3] - mn1); sum1 += S[j][3];
        }
        sum0 += __shfl_xor_sync(0xffffffffu, sum0, 1);
        sum0 += __shfl_xor_sync(0xffffffffu, sum0, 2);
        sum1 += __shfl_xor_sync(0xffffffffu, sum1, 1);
        sum1 += __shfl_xor_sync(0xffffffffu, sum1, 2);
        l0 = l0 * a0 + sum0;
        l1 = l1 * a1 + sum1;

        #pragma unroll
        for (int j = 0; j < 8; j++) {
            O[j][0] *= a0; O[j][1] *= a0; O[j][2] *= a1; O[j][3] *= a1;
        }

        // ---- P -> single fp16 A-fragments ----
        uint32_t ph[4][4];
        #pragma unroll
        for (int kc = 0; kc < 4; kc++) {
            const float* x = S[2 * kc];
            const float* y = S[2 * kc + 1];
            ph[kc][0] = pack_h(__float2half_rn(x[0]), __float2half_rn(x[1]));
            ph[kc][1] = pack_h(__float2half_rn(x[2]), __float2half_rn(x[3]));
            ph[kc][2] = pack_h(__float2half_rn(y[0]), __float2half_rn(y[1]));
            ph[kc][3] = pack_h(__float2half_rn(y[2]), __float2half_rn(y[3]));
        }

        // ---- O += P V; V via ldmatrix.trans ----
        #pragma unroll
        for (int jn = 0; jn < 8; jn++) {
            #pragma unroll
            for (int kc = 0; kc < 4; kc++) {
                int vrow = kc * 16 + (lane & 15);
                uint32_t vh0, vh1;
                ldsm_x2t(vh0, vh1, smem_u32(vb + vrow * FST + jn * 8));
                mma_f16(O[jn], ph[kc][0], ph[kc][1], ph[kc][2], ph[kc][3], vh0, vh1);
            }
        }
    }

    // ---- normalize + write fp16 ----
    float inv0 = l0 > 0.0f ? 1.0f / l0 : 0.0f;
    float inv1 = l1 > 0.0f ? 1.0f / l1 : 0.0f;
    int row0 = grow0 + warp * 16 + (lane >> 2);
    int col  = ghc + ((lane & 3) << 1);
    #pragma unroll
    for (int jn = 0; jn < 8; jn++) {
        *reinterpret_cast<uint32_t*>(Oh + (size_t)row0 * D_ + col + jn * 8) =
            pack_h(__float2half_rn(O[jn][0] * inv0), __float2half_rn(O[jn][1] * inv0));
        *reinterpret_cast<uint32_t*>(Oh + (size_t)(row0 + 8) * D_ + col + jn * 8) =
            pack_h(__float2half_rn(O[jn][2] * inv1), __float2half_rn(O[jn][3] * inv1));
    }
}

// ---------------------------------------------------------------------------
// Launch
// ---------------------------------------------------------------------------
extern "C" void kernel_launch(void* const* d_in, const int* in_sizes, int n_in,
                              void* d_out, int out_size)
{
    const float* query = (const float*)d_in[0];
    const float* key   = (const float*)d_in[1];
    const float* value = (const float*)d_in[2];
    const int*   mask  = (const int*)d_in[3];
    const float* Wq = (const float*)d_in[4];
    const float* bq = (const float*)d_in[5];
    const float* Wk = (const float*)d_in[6];
    const float* bk = (const float*)d_in[7];
    const float* Wv = (const float*)d_in[8];
    const float* bv = (const float*)d_in[9];
    const float* Wo = (const float*)d_in[10];
    const float* bo = (const float*)d_in[11];
    float* out = (float*)d_out;

    void *p[12];
    cudaGetSymbolAddress(&p[0],  g_Iqh);  cudaGetSymbolAddress(&p[1],  g_Iql);
    cudaGetSymbolAddress(&p[2],  g_Ikh);  cudaGetSymbolAddress(&p[3],  g_Ivh);
    cudaGetSymbolAddress(&p[4],  g_Wq16); cudaGetSymbolAddress(&p[5],  g_Wk16);
    cudaGetSymbolAddress(&p[6],  g_Wv16); cudaGetSymbolAddress(&p[7],  g_Wo16);
    cudaGetSymbolAddress(&p[8],  g_Qhi);
    cudaGetSymbolAddress(&p[9],  g_Khi);  cudaGetSymbolAddress(&p[10], g_Vhi);
    cudaGetSymbolAddress(&p[11], g_Athi);
    __half* Iqh = (__half*)p[0];  __half* Iql = (__half*)p[1];
    __half* Ikh = (__half*)p[2];  __half* Ivh = (__half*)p[3];
    __half* Wq16 = (__half*)p[4]; __half* Wk16 = (__half*)p[5];
    __half* Wv16 = (__half*)p[6]; __half* Wo16 = (__half*)p[7];
    __half* Qhi = (__half*)p[8];
    __half* Khi = (__half*)p[9];  __half* Vhi = (__half*)p[10];
    __half* Athi = (__half*)p[11];

    cudaFuncSetAttribute(gemm_f16_multi,
                         cudaFuncAttributeMaxDynamicSharedMemorySize, GSMEM);
    cudaFuncSetAttribute(flash_hmma_kernel,
                         cudaFuncAttributeMaxDynamicSharedMemorySize, FSMEM);

    prep_kernel<<<dim3(512, 1, 7), 256>>>(
        query, key, value, Wq, Wk, Wv, Wo,
        Iqh, Iql, Ikh, Ivh, Wq16, Wk16, Wv16, Wo16);

    // Q pre-scale folds 1/sqrt(HD) AND log2(e) for exp2-domain softmax
    GemmArgs qa = { Iqh, Iql, Wq16, bq, nullptr, Qhi, nullptr, 1, 0.125f * 1.44269504f };
    GemmArgs ka = { Ikh, nullptr, Wk16, bk, nullptr, Khi, nullptr, 0, 1.0f };
    GemmArgs va = { Ivh, nullptr, Wv16, bv, nullptr, Vhi, nullptr, 0, 1.0f };
    GemmArgs oa = { Athi, nullptr, Wo16, bo, out, nullptr, nullptr, 0, 1.0f };

    gemm_f16_multi<<<dim3(D_ / 128, M_TOT / 128, 3), 256, GSMEM>>>(qa, ka, va);

    flash_hmma_kernel<<<dim3(L_ / 128, H_, B_), 256, FSMEM>>>(
        Qhi, Khi, Vhi, mask, Athi);

    gemm_f16_multi<<<dim3(D_ / 128, M_TOT / 128, 1), 256, GSMEM>>>(oa, oa, oa);
}

// round 15
// speedup vs baseline: 1.5020x; 1.5020x over previous
#include <cuda_runtime.h>
#include <cuda_fp16.h>
#include <cstdint>

#define B_   4
#define L_   1024
#define D_   1024
#define H_   16
#define HD_  64
#define M_TOT (B_ * L_)   // 4096

// Scratch (static device globals — allocation-guard safe)
__device__ __half g_Iqh[M_TOT * D_], g_Iql[M_TOT * D_];   // query input split (2-term)
__device__ __half g_Ikh[M_TOT * D_];                      // key input (1-term)
__device__ __half g_Ivh[M_TOT * D_];                      // value input (1-term)
__device__ __half g_Wq16[D_ * D_], g_Wk16[D_ * D_], g_Wv16[D_ * D_], g_Wo16[D_ * D_];
__device__ __half g_Qhi[M_TOT * D_];                      // Q projected (fp16, pre-scaled 0.125*log2e)
__device__ __half g_Khi[M_TOT * D_], g_Vhi[M_TOT * D_];
__device__ __half g_Athi[M_TOT * D_];                     // attention out (fp16)

// ===========================================================================
// Helpers
// ===========================================================================
__device__ __forceinline__ uint32_t smem_u32(const void* p) {
    uint32_t a;
    asm("{ .reg .u64 t; cvta.to.shared.u64 t, %1; cvt.u32.u64 %0, t; }" : "=r"(a) : "l"(p));
    return a;
}
__device__ __forceinline__ void ldsm_x4(uint32_t& r0, uint32_t& r1, uint32_t& r2, uint32_t& r3, uint32_t a) {
    asm volatile("ldmatrix.sync.aligned.m8n8.x4.shared.b16 {%0,%1,%2,%3}, [%4];"
                 : "=r"(r0), "=r"(r1), "=r"(r2), "=r"(r3) : "r"(a));
}
__device__ __forceinline__ void ldsm_x2(uint32_t& r0, uint32_t& r1, uint32_t a) {
    asm volatile("ldmatrix.sync.aligned.m8n8.x2.shared.b16 {%0,%1}, [%2];"
                 : "=r"(r0), "=r"(r1) : "r"(a));
}
__device__ __forceinline__ void ldsm_x2t(uint32_t& r0, uint32_t& r1, uint32_t a) {
    asm volatile("ldmatrix.sync.aligned.m8n8.x2.trans.shared.b16 {%0,%1}, [%2];"
                 : "=r"(r0), "=r"(r1) : "r"(a));
}
__device__ __forceinline__ void mma_f16(float* c,
    uint32_t a0, uint32_t a1, uint32_t a2, uint32_t a3, uint32_t b0, uint32_t b1) {
    asm volatile("mma.sync.aligned.m16n8k16.row.col.f32.f16.f16.f32 "
                 "{%0,%1,%2,%3}, {%4,%5,%6,%7}, {%8,%9}, {%0,%1,%2,%3};"
                 : "+f"(c[0]), "+f"(c[1]), "+f"(c[2]), "+f"(c[3])
                 : "r"(a0), "r"(a1), "r"(a2), "r"(a3), "r"(b0), "r"(b1));
}
__device__ __forceinline__ uint32_t pack_h(__half lo, __half hi) {
    return ((uint32_t)__half_as_ushort(hi) << 16) | __half_as_ushort(lo);
}
__device__ __forceinline__ void split2h(float x, __half& h, __half& l) {
    h = __float2half_rn(x);
    l = __float2half_rn(x - __half2float(h));
}
__device__ __forceinline__ void cp16(uint32_t dst, const void* src) {
    asm volatile("cp.async.cg.shared.global [%0], [%1], 16;" :: "r"(dst), "l"(src));
}
__device__ __forceinline__ void cp_commit() { asm volatile("cp.async.commit_group;"); }
template<int N> __device__ __forceinline__ void cp_wait() {
    asm volatile("cp.async.wait_group %0;" :: "n"(N));
}

// ===========================================================================
// Prep: query -> hi/lo split; key/value/weights -> single fp16.  grid (512,1,7)
// ===========================================================================
__global__ __launch_bounds__(256) void prep_kernel(
    const float* __restrict__ q, const float* __restrict__ k, const float* __restrict__ v,
    const float* __restrict__ wq, const float* __restrict__ wk,
    const float* __restrict__ wv, const float* __restrict__ wo,
    __half* qh, __half* ql, __half* kh, __half* vh,
    __half* wqh, __half* wkh, __half* wvh, __half* woh)
{
    const int z = blockIdx.z;
    const int base = blockIdx.x * 256 + threadIdx.x;
    if (z == 0) {
        #pragma unroll
        for (int i = 0; i < 8; i++) {
            int e4 = base + i * 131072;
            float4 x = reinterpret_cast<const float4*>(q)[e4];
            __half h0, h1, h2, h3, l0, l1, l2, l3;
            split2h(x.x, h0, l0); split2h(x.y, h1, l1);
            split2h(x.z, h2, l2); split2h(x.w, h3, l3);
            uint2 hv = { pack_h(h0, h1), pack_h(h2, h3) };
            uint2 lv = { pack_h(l0, l1), pack_h(l2, l3) };
            *reinterpret_cast<uint2*>(qh + (size_t)e4 * 4) = hv;
            *reinterpret_cast<uint2*>(ql + (size_t)e4 * 4) = lv;
        }
    } else if (z < 3) {
        const float* src = (z == 1) ? k : v;
        __half* dst = (z == 1) ? kh : vh;
        #pragma unroll
        for (int i = 0; i < 8; i++) {
            int e4 = base + i * 131072;
            float4 x = reinterpret_cast<const float4*>(src)[e4];
            uint2 hv = { pack_h(__float2half_rn(x.x), __float2half_rn(x.y)),
                         pack_h(__float2half_rn(x.z), __float2half_rn(x.w)) };
            *reinterpret_cast<uint2*>(dst + (size_t)e4 * 4) = hv;
        }
    } else {
        const float* src = (z == 3) ? wq : (z == 4) ? wk : (z == 5) ? wv : wo;
        __half* dst = (z == 3) ? wqh : (z == 4) ? wkh : (z == 5) ? wvh : woh;
        #pragma unroll
        for (int i = 0; i < 2; i++) {
            int e4 = base + i * 131072;
            float4 x = reinterpret_cast<const float4*>(src)[e4];
            uint2 wv2 = { pack_h(__float2half_rn(x.x), __float2half_rn(x.y)),
                          pack_h(__float2half_rn(x.z), __float2half_rn(x.w)) };
            *reinterpret_cast<uint2*>(dst + (size_t)e4 * 4) = wv2;
        }
    }
}

// ===========================================================================
// fp16 HMMA GEMM, cp.async double-buffered (R13 structure).
//   C = (Ah [+ Al]) @ Wh^T + bias, then * oscale.
// ===========================================================================
#define BKC   32
#define NCH   (D_ / BKC)   // 32
#define SST   40
#define ARR_H (128 * SST)
#define STG_H (3 * ARR_H)
#define GSMEM (2 * STG_H * 2)          // 61440 bytes

struct GemmArgs {
    const __half* Ah;
    const __half* Al;
    const __half* Wh;
    const float*  bias;
    float*  C;
    __half* Chi;
    __half* Clo;
    int     two_term;   // A-side lo term present
    float   oscale;     // output scale (applied after bias)
};

__device__ __forceinline__ void issue_chunk(
    const GemmArgs& g, int m0, int n0, int k0, int t, uint32_t stage_b)
{
    #pragma unroll
    for (int i = 0; i < 2; i++) {
        int s  = t + (i << 8);
        int r  = s >> 2;
        int c8 = (s & 3) << 3;
        uint32_t d = stage_b + (uint32_t)(r * SST + c8) * 2;
        size_t goff = (size_t)(m0 + r) * D_ + k0 + c8;
        cp16(d, g.Ah + goff);
        if (g.two_term) cp16(d + ARR_H * 2, g.Al + goff);
        cp16(d + 2 * ARR_H * 2, g.Wh + (size_t)(n0 + r) * D_ + k0 + c8);
    }
}

__global__ __launch_bounds__(256, 2) void gemm_f16_multi(
    GemmArgs ga0, GemmArgs ga1, GemmArgs ga2)
{
    extern __shared__ __half dsm[];
    const GemmArgs g = (blockIdx.z == 0) ? ga0 : ((blockIdx.z == 1) ? ga1 : ga2);

    const int t    = threadIdx.x;
    const int lane = t & 31;
    const int warp = t >> 5;
    const int wm   = warp >> 2;
    const int wn   = warp & 3;
    const int m0   = blockIdx.y * 128;
    const int n0   = blockIdx.x * 128;
    const uint32_t sb = smem_u32(dsm);

    float acc[4][4][4];
    #pragma unroll
    for (int i = 0; i < 4; i++)
        #pragma unroll
        for (int j = 0; j < 4; j++)
            #pragma unroll
            for (int r = 0; r < 4; r++) acc[i][j][r] = 0.0f;

    issue_chunk(g, m0, n0, 0, t, sb);
    cp_commit();
    issue_chunk(g, m0, n0, BKC, t, sb + STG_H * 2);
    cp_commit();

    for (int ck = 0; ck < NCH; ck++) {
        const int st = ck & 1;
        const __half* cah = dsm + st * STG_H;
        const __half* cal = cah + ARR_H;
        const __half* cbh = cah + 2 * ARR_H;

        if (ck + 1 < NCH) cp_wait<1>(); else cp_wait<0>();
        __syncthreads();

        #pragma unroll
        for (int ks = 0; ks < 2; ks++) {
            const int k0 = ks * 16;
            uint32_t bh[4][2];
            #pragma unroll
            for (int j = 0; j < 4; j++) {
                int row = wn * 32 + j * 8 + (lane & 7);
                int col = k0 + (((lane >> 3) & 1) << 3);
                ldsm_x2(bh[j][0], bh[j][1], smem_u32(cbh + row * SST + col));
            }
            #pragma unroll
            for (int i = 0; i < 4; i++) {
                int row = wm * 64 + i * 16 + (lane & 15);
                int col = k0 + ((lane >> 4) << 3);
                uint32_t ah0, ah1, ah2, ah3;
                ldsm_x4(ah0, ah1, ah2, ah3, smem_u32(cah + row * SST + col));
                #pragma unroll
                for (int j = 0; j < 4; j++)
                    mma_f16(acc[i][j], ah0, ah1, ah2, ah3, bh[j][0], bh[j][1]);
                if (g.two_term) {
                    uint32_t al0, al1, al2, al3;
                    ldsm_x4(al0, al1, al2, al3, smem_u32(cal + row * SST + col));
                    #pragma unroll
                    for (int j = 0; j < 4; j++)
                        mma_f16(acc[i][j], al0, al1, al2, al3, bh[j][0], bh[j][1]);
                }
            }
        }
        __syncthreads();

        if (ck + 2 < NCH) {
            issue_chunk(g, m0, n0, (ck + 2) * BKC, t, sb + st * STG_H * 2);
            cp_commit();
        }
    }

    const int lr = lane >> 2;
    const int lc = (lane & 3) << 1;
    #pragma unroll
    for (int i = 0; i < 4; i++) {
        #pragma unroll
        for (int j = 0; j < 4; j++) {
            int row = m0 + wm * 64 + i * 16 + lr;
            int col = n0 + wn * 32 + j * 8 + lc;
            float2 bz = *reinterpret_cast<const float2*>(g.bias + col);
            float v0 = (acc[i][j][0] + bz.x) * g.oscale;
            float v1 = (acc[i][j][1] + bz.y) * g.oscale;
            float v2 = (acc[i][j][2] + bz.x) * g.oscale;
            float v3 = (acc[i][j][3] + bz.y) * g.oscale;
            if (g.Chi) {
                if (g.Clo) {
                    __half h0, h1, h2, h3, l0, l1, l2, l3;
                    split2h(v0, h0, l0); split2h(v1, h1, l1);
                    split2h(v2, h2, l2); split2h(v3, h3, l3);
                    *reinterpret_cast<uint32_t*>(g.Chi + (size_t)row * D_ + col)       = pack_h(h0, h1);
                    *reinterpret_cast<uint32_t*>(g.Clo + (size_t)row * D_ + col)       = pack_h(l0, l1);
                    *reinterpret_cast<uint32_t*>(g.Chi + (size_t)(row + 8) * D_ + col) = pack_h(h2, h3);
                    *reinterpret_cast<uint32_t*>(g.Clo + (size_t)(row + 8) * D_ + col) = pack_h(l2, l3);
                } else {
                    *reinterpret_cast<uint32_t*>(g.Chi + (size_t)row * D_ + col) =
                        pack_h(__float2half_rn(v0), __float2half_rn(v1));
                    *reinterpret_cast<uint32_t*>(g.Chi + (size_t)(row + 8) * D_ + col) =
                        pack_h(__float2half_rn(v2), __float2half_rn(v3));
                }
            } else {
                float2 o0 = { v0, v1 }, o1 = { v2, v3 };
                *reinterpret_cast<float2*>(g.C + (size_t)row * D_ + col) = o0;
                *reinterpret_cast<float2*>(g.C + (size_t)(row + 8) * D_ + col) = o1;
            }
        }
    }
}

// ===========================================================================
// HMMA flash attention (R13 structure): Q/K/V/P/At single fp16.
// Q pre-scaled by 0.125*log2e -> softmax in exp2 domain.
// ===========================================================================
#define FST 72

__global__ __launch_bounds__(256) void flash_hmma_kernel(
    const __half* __restrict__ Qhi,
    const __half* __restrict__ Khi, const __half* __restrict__ Vhi,
    const int* __restrict__ mask,
    __half* __restrict__ Oh)
{
    __shared__ __align__(16) __half KH[2][64][FST];
    __shared__ __align__(16) __half VH[2][64][FST];
    __shared__ int MI[2][64];

    const int t    = threadIdx.x;
    const int lane = t & 31;
    const int warp = t >> 5;
    const int qt   = blockIdx.x;
    const int h    = blockIdx.y;
    const int b    = blockIdx.z;
    const int grow0 = b * L_ + qt * 128;
    const int ghc   = h * HD_;

    // ---- stage Q tile (128 rows, hi only) through KH[0]|VH[0] ----
    #pragma unroll
    for (int i = 0; i < 2; i++) {
        int v = t + i * 256;       // 0..511
        int r = v >> 2;            // 0..127
        int c = (v & 3) << 4;      // 0,16,32,48
        __half* dh = (r < 64) ? &KH[0][r][c] : &VH[0][r - 64][c];
        *reinterpret_cast<uint4*>(dh) =
            *reinterpret_cast<const uint4*>(Qhi + (size_t)(grow0 + r) * D_ + ghc + c);
        *reinterpret_cast<uint4*>(dh + 8) =
            *reinterpret_cast<const uint4*>(Qhi + (size_t)(grow0 + r) * D_ + ghc + c + 8);
    }
    __syncthreads();

    uint32_t qh[4][4];
    {
        int ar = warp * 16 + (lane & 15);
        int ac = (lane >> 4) << 3;
        const __half* sh = (ar < 64) ? &KH[0][ar][0] : &VH[0][ar - 64][0];
        #pragma unroll
        for (int kc = 0; kc < 4; kc++)
            ldsm_x4(qh[kc][0], qh[kc][1], qh[kc][2], qh[kc][3], smem_u32(sh + kc * 16 + ac));
    }
    __syncthreads();   // Q fragments read; smem stages free for K/V

    float O[8][4];
    #pragma unroll
    for (int j = 0; j < 8; j++)
        #pragma unroll
        for (int r = 0; r < 4; r++) O[j][r] = 0.0f;
    float m0 = -1e30f, m1 = -1e30f, l0 = 0.0f, l1 = 0.0f;

    auto issue_kv = [&](int tile, int st) {
        const int krow0 = b * L_ + tile * 64;
        #pragma unroll
        for (int i = 0; i < 2; i++) {
            int s = t + i * 256;
            int r = s >> 3;
            int c = (s & 7) << 3;
            size_t gb = (size_t)(krow0 + r) * D_ + ghc + c;
            cp16(smem_u32(&KH[st][r][c]), Khi + gb);
            cp16(smem_u32(&VH[st][r][c]), Vhi + gb);
        }
        if (t < 16) cp16(smem_u32(&MI[st][t * 4]), mask + b * L_ + tile * 64 + t * 4);
        cp_commit();
    };

    issue_kv(0, 0);
    issue_kv(1, 1);

    for (int kt = 0; kt < 16; kt++) {
        const int st = kt & 1;
        if (kt + 1 < 16) cp_wait<1>(); else cp_wait<0>();
        __syncthreads();

        // ---- S = Q K^T (single term, Q pre-scaled incl. log2e) ----
        float S[8][4];
        #pragma unroll
        for (int j = 0; j < 8; j++) {
            S[j][0] = S[j][1] = S[j][2] = S[j][3] = 0.0f;
            int brow = j * 8 + (lane & 7);
            #pragma unroll
            for (int kc = 0; kc < 4; kc++) {
                int bcol = kc * 16 + (((lane >> 3) & 1) << 3);
                uint32_t bh0, bh1;
                ldsm_x2(bh0, bh1, smem_u32(&KH[st][brow][bcol]));
                mma_f16(S[j], qh[kc][0], qh[kc][1], qh[kc][2], qh[kc][3], bh0, bh1);
            }
        }

        // ---- softmax in exp2 domain ----
        float rmax0 = -3.0e38f, rmax1 = -3.0e38f;
        #pragma unroll
        for (int j = 0; j < 8; j++) {
            int cidx = j * 8 + ((lane & 3) << 1);
            float ma = MI[st][cidx]     ? -1e30f : 0.0f;
            float mb = MI[st][cidx + 1] ? -1e30f : 0.0f;
            S[j][0] += ma; S[j][1] += mb; S[j][2] += ma; S[j][3] += mb;
            rmax0 = fmaxf(rmax0, fmaxf(S[j][0], S[j][1]));
            rmax1 = fmaxf(rmax1, fmaxf(S[j][2], S[j][3]));
        }
        rmax0 = fmaxf(rmax0, __shfl_xor_sync(0xffffffffu, rmax0, 1));
        rmax0 = fmaxf(rmax0, __shfl_xor_sync(0xffffffffu, rmax0, 2));
        rmax1 = fmaxf(rmax1, __shfl_xor_sync(0xffffffffu, rmax1, 1));
        rmax1 = fmaxf(rmax1, __shfl_xor_sync(0xffffffffu, rmax1, 2));

        float mn0 = fmaxf(m0, rmax0), mn1 = fmaxf(m1, rmax1);
        float a0 = exp2f(m0 - mn0), a1 = exp2f(m1 - mn1);
        m0 = mn0; m1 = mn1;

        float sum0 = 0.0f, sum1 = 0.0f;
        #pragma unroll
        for (int j = 0; j < 8; j++) {
            S[j][0] = exp2f(S[j][0] - mn0); sum0 += S[j][0];
            S[j][1] = exp2f(S[j][1] - mn0); sum0 += S[j][1];
            S[j][2] = exp2f(S[j][2] - mn1); sum1 += S[j][2];
            S[j][3] = exp2f(S[j][3] - mn1); sum1 += S[j][3];
        }
        sum0 += __shfl_xor_sync(0xffffffffu, sum0, 1);
        sum0 += __shfl_xor_sync(0xffffffffu, sum0, 2);
        sum1 += __shfl_xor_sync(0xffffffffu, sum1, 1);
        sum1 += __shfl_xor_sync(0xffffffffu, sum1, 2);
        l0 = l0 * a0 + sum0;
        l1 = l1 * a1 + sum1;

        #pragma unroll
        for (int j = 0; j < 8; j++) {
            O[j][0] *= a0; O[j][1] *= a0; O[j][2] *= a1; O[j][3] *= a1;
        }

        // ---- P -> single fp16 A-fragments ----
        uint32_t ph[4][4];
        #pragma unroll
        for (int kc = 0; kc < 4; kc++) {
            const float* x = S[2 * kc];
            const float* y = S[2 * kc + 1];
            ph[kc][0] = pack_h(__float2half_rn(x[0]), __float2half_rn(x[1]));
            ph[kc][1] = pack_h(__float2half_rn(x[2]), __float2half_rn(x[3]));
            ph[kc][2] = pack_h(__float2half_rn(y[0]), __float2half_rn(y[1]));
            ph[kc][3] = pack_h(__float2half_rn(y[2]), __float2half_rn(y[3]));
        }

        // ---- O += P V (single term); V via ldmatrix.trans ----
        #pragma unroll
        for (int jn = 0; jn < 8; jn++) {
            #pragma unroll
            for (int kc = 0; kc < 4; kc++) {
                int vrow = kc * 16 + (lane & 15);
                uint32_t vh0, vh1;
                ldsm_x2t(vh0, vh1, smem_u32(&VH[st][vrow][jn * 8]));
                mma_f16(O[jn], ph[kc][0], ph[kc][1], ph[kc][2], ph[kc][3], vh0, vh1);
            }
        }
        __syncthreads();

        if (kt + 2 < 16) issue_kv(kt + 2, st);
    }

    // ---- normalize + write fp16 ----
    float inv0 = l0 > 0.0f ? 1.0f / l0 : 0.0f;
    float inv1 = l1 > 0.0f ? 1.0f / l1 : 0.0f;
    int row0 = grow0 + warp * 16 + (lane >> 2);
    int col  = ghc + ((lane & 3) << 1);
    #pragma unroll
    for (int jn = 0; jn < 8; jn++) {
        *reinterpret_cast<uint32_t*>(Oh + (size_t)row0 * D_ + col + jn * 8) =
            pack_h(__float2half_rn(O[jn][0] * inv0), __float2half_rn(O[jn][1] * inv0));
        *reinterpret_cast<uint32_t*>(Oh + (size_t)(row0 + 8) * D_ + col + jn * 8) =
            pack_h(__float2half_rn(O[jn][2] * inv1), __float2half_rn(O[jn][3] * inv1));
    }
}

// ---------------------------------------------------------------------------
// Launch
// ---------------------------------------------------------------------------
extern "C" void kernel_launch(void* const* d_in, const int* in_sizes, int n_in,
                              void* d_out, int out_size)
{
    const float* query = (const float*)d_in[0];
    const float* key   = (const float*)d_in[1];
    const float* value = (const float*)d_in[2];
    const int*   mask  = (const int*)d_in[3];
    const float* Wq = (const float*)d_in[4];
    const float* bq = (const float*)d_in[5];
    const float* Wk = (const float*)d_in[6];
    const float* bk = (const float*)d_in[7];
    const float* Wv = (const float*)d_in[8];
    const float* bv = (const float*)d_in[9];
    const float* Wo = (const float*)d_in[10];
    const float* bo = (const float*)d_in[11];
    float* out = (float*)d_out;

    void *p[12];
    cudaGetSymbolAddress(&p[0],  g_Iqh);  cudaGetSymbolAddress(&p[1],  g_Iql);
    cudaGetSymbolAddress(&p[2],  g_Ikh);  cudaGetSymbolAddress(&p[3],  g_Ivh);
    cudaGetSymbolAddress(&p[4],  g_Wq16); cudaGetSymbolAddress(&p[5],  g_Wk16);
    cudaGetSymbolAddress(&p[6],  g_Wv16); cudaGetSymbolAddress(&p[7],  g_Wo16);
    cudaGetSymbolAddress(&p[8],  g_Qhi);
    cudaGetSymbolAddress(&p[9],  g_Khi);  cudaGetSymbolAddress(&p[10], g_Vhi);
    cudaGetSymbolAddress(&p[11], g_Athi);
    __half* Iqh = (__half*)p[0];  __half* Iql = (__half*)p[1];
    __half* Ikh = (__half*)p[2];  __half* Ivh = (__half*)p[3];
    __half* Wq16 = (__half*)p[4]; __half* Wk16 = (__half*)p[5];
    __half* Wv16 = (__half*)p[6]; __half* Wo16 = (__half*)p[7];
    __half* Qhi = (__half*)p[8];
    __half* Khi = (__half*)p[9];  __half* Vhi = (__half*)p[10];
    __half* Athi = (__half*)p[11];

    cudaFuncSetAttribute(gemm_f16_multi,
                         cudaFuncAttributeMaxDynamicSharedMemorySize, GSMEM);

    prep_kernel<<<dim3(512, 1, 7), 256>>>(
        query, key, value, Wq, Wk, Wv, Wo,
        Iqh, Iql, Ikh, Ivh, Wq16, Wk16, Wv16, Wo16);

    // Q pre-scale folds 1/sqrt(HD) AND log2(e) for exp2-domain softmax
    GemmArgs qa = { Iqh, Iql, Wq16, bq, nullptr, Qhi, nullptr, 1, 0.125f * 1.44269504f };
    GemmArgs ka = { Ikh, nullptr, Wk16, bk, nullptr, Khi, nullptr, 0, 1.0f };
    GemmArgs va = { Ivh, nullptr, Wv16, bv, nullptr, Vhi, nullptr, 0, 1.0f };
    GemmArgs oa = { Athi, nullptr, Wo16, bo, out, nullptr, nullptr, 0, 1.0f };

    gemm_f16_multi<<<dim3(D_ / 128, M_TOT / 128, 3), 256, GSMEM>>>(qa, ka, va);

    flash_hmma_kernel<<<dim3(L_ / 128, H_, B_), 256>>>(
        Qhi, Khi, Vhi, mask, Athi);

    gemm_f16_multi<<<dim3(D_ / 128, M_TOT / 128, 1), 256, GSMEM>>>(oa, oa, oa);
}

// round 16
// speedup vs baseline: 1.5181x; 1.0107x over previous
#include <cuda_runtime.h>
#include <cuda_fp16.h>
#include <cstdint>

#define B_   4
#define L_   1024
#define D_   1024
#define H_   16
#define HD_  64
#define M_TOT (B_ * L_)   // 4096

// Scratch (static device globals — allocation-guard safe)
__device__ __half g_Iqh[M_TOT * D_], g_Iql[M_TOT * D_];   // query input split (2-term)
__device__ __half g_Ikh[M_TOT * D_];                      // key input (1-term)
__device__ __half g_Ivh[M_TOT * D_];                      // value input (1-term)
__device__ __half g_Wq16[D_ * D_], g_Wk16[D_ * D_], g_Wv16[D_ * D_], g_Wo16[D_ * D_];
__device__ __half g_Qhi[M_TOT * D_];                      // Q projected (fp16, pre-scaled 0.125*log2e)
__device__ __half g_Khi[M_TOT * D_], g_Vhi[M_TOT * D_];
__device__ __half g_Athi[M_TOT * D_];                     // attention out (fp16)

// ===========================================================================
// Helpers
// ===========================================================================
__device__ __forceinline__ uint32_t smem_u32(const void* p) {
    uint32_t a;
    asm("{ .reg .u64 t; cvta.to.shared.u64 t, %1; cvt.u32.u64 %0, t; }" : "=r"(a) : "l"(p));
    return a;
}
__device__ __forceinline__ void ldsm_x4(uint32_t& r0, uint32_t& r1, uint32_t& r2, uint32_t& r3, uint32_t a) {
    asm volatile("ldmatrix.sync.aligned.m8n8.x4.shared.b16 {%0,%1,%2,%3}, [%4];"
                 : "=r"(r0), "=r"(r1), "=r"(r2), "=r"(r3) : "r"(a));
}
__device__ __forceinline__ void ldsm_x2(uint32_t& r0, uint32_t& r1, uint32_t a) {
    asm volatile("ldmatrix.sync.aligned.m8n8.x2.shared.b16 {%0,%1}, [%2];"
                 : "=r"(r0), "=r"(r1) : "r"(a));
}
__device__ __forceinline__ void ldsm_x4t(uint32_t& r0, uint32_t& r1, uint32_t& r2, uint32_t& r3, uint32_t a) {
    asm volatile("ldmatrix.sync.aligned.m8n8.x4.trans.shared.b16 {%0,%1,%2,%3}, [%4];"
                 : "=r"(r0), "=r"(r1), "=r"(r2), "=r"(r3) : "r"(a));
}
__device__ __forceinline__ void mma_f16(float* c,
    uint32_t a0, uint32_t a1, uint32_t a2, uint32_t a3, uint32_t b0, uint32_t b1) {
    asm volatile("mma.sync.aligned.m16n8k16.row.col.f32.f16.f16.f32 "
                 "{%0,%1,%2,%3}, {%4,%5,%6,%7}, {%8,%9}, {%0,%1,%2,%3};"
                 : "+f"(c[0]), "+f"(c[1]), "+f"(c[2]), "+f"(c[3])
                 : "r"(a0), "r"(a1), "r"(a2), "r"(a3), "r"(b0), "r"(b1));
}
__device__ __forceinline__ uint32_t pack_h(__half lo, __half hi) {
    return ((uint32_t)__half_as_ushort(hi) << 16) | __half_as_ushort(lo);
}
__device__ __forceinline__ void split2h(float x, __half& h, __half& l) {
    h = __float2half_rn(x);
    l = __float2half_rn(x - __half2float(h));
}
__device__ __forceinline__ void cp16(uint32_t dst, const void* src) {
    asm volatile("cp.async.cg.shared.global [%0], [%1], 16;" :: "r"(dst), "l"(src));
}
__device__ __forceinline__ void cp_commit() { asm volatile("cp.async.commit_group;"); }
template<int N> __device__ __forceinline__ void cp_wait() {
    asm volatile("cp.async.wait_group %0;" :: "n"(N));
}

// ===========================================================================
// Prep: query -> hi/lo split; key/value/weights -> single fp16.  grid (512,1,7)
// ===========================================================================
__global__ __launch_bounds__(256) void prep_kernel(
    const float* __restrict__ q, const float* __restrict__ k, const float* __restrict__ v,
    const float* __restrict__ wq, const float* __restrict__ wk,
    const float* __restrict__ wv, const float* __restrict__ wo,
    __half* qh, __half* ql, __half* kh, __half* vh,
    __half* wqh, __half* wkh, __half* wvh, __half* woh)
{
    const int z = blockIdx.z;
    const int base = blockIdx.x * 256 + threadIdx.x;
    if (z == 0) {
        #pragma unroll
        for (int i = 0; i < 8; i++) {
            int e4 = base + i * 131072;
            float4 x = reinterpret_cast<const float4*>(q)[e4];
            __half h0, h1, h2, h3, l0, l1, l2, l3;
            split2h(x.x, h0, l0); split2h(x.y, h1, l1);
            split2h(x.z, h2, l2); split2h(x.w, h3, l3);
            uint2 hv = { pack_h(h0, h1), pack_h(h2, h3) };
            uint2 lv = { pack_h(l0, l1), pack_h(l2, l3) };
            *reinterpret_cast<uint2*>(qh + (size_t)e4 * 4) = hv;
            *reinterpret_cast<uint2*>(ql + (size_t)e4 * 4) = lv;
        }
    } else if (z < 3) {
        const float* src = (z == 1) ? k : v;
        __half* dst = (z == 1) ? kh : vh;
        #pragma unroll
        for (int i = 0; i < 8; i++) {
            int e4 = base + i * 131072;
            float4 x = reinterpret_cast<const float4*>(src)[e4];
            uint2 hv = { pack_h(__float2half_rn(x.x), __float2half_rn(x.y)),
                         pack_h(__float2half_rn(x.z), __float2half_rn(x.w)) };
            *reinterpret_cast<uint2*>(dst + (size_t)e4 * 4) = hv;
        }
    } else {
        const float* src = (z == 3) ? wq : (z == 4) ? wk : (z == 5) ? wv : wo;
        __half* dst = (z == 3) ? wqh : (z == 4) ? wkh : (z == 5) ? wvh : woh;
        #pragma unroll
        for (int i = 0; i < 2; i++) {
            int e4 = base + i * 131072;
            float4 x = reinterpret_cast<const float4*>(src)[e4];
            uint2 wv2 = { pack_h(__float2half_rn(x.x), __float2half_rn(x.y)),
                          pack_h(__float2half_rn(x.z), __float2half_rn(x.w)) };
            *reinterpret_cast<uint2*>(dst + (size_t)e4 * 4) = wv2;
        }
    }
}

// ===========================================================================
// fp16 HMMA GEMM, cp.async double-buffered (R13/R15 proven structure — UNCHANGED).
//   C = (Ah [+ Al]) @ Wh^T + bias, then * oscale.
// ===========================================================================
#define BKC   32
#define NCH   (D_ / BKC)   // 32
#define SST   40
#define ARR_H (128 * SST)
#define STG_H (3 * ARR_H)
#define GSMEM (2 * STG_H * 2)          // 61440 bytes

struct GemmArgs {
    const __half* Ah;
    const __half* Al;
    const __half* Wh;
    const float*  bias;
    float*  C;
    __half* Chi;
    __half* Clo;
    int     two_term;   // A-side lo term present
    float   oscale;     // output scale (applied after bias)
};

__device__ __forceinline__ void issue_chunk(
    const GemmArgs& g, int m0, int n0, int k0, int t, uint32_t stage_b)
{
    #pragma unroll
    for (int i = 0; i < 2; i++) {
        int s  = t + (i << 8);
        int r  = s >> 2;
        int c8 = (s & 3) << 3;
        uint32_t d = stage_b + (uint32_t)(r * SST + c8) * 2;
        size_t goff = (size_t)(m0 + r) * D_ + k0 + c8;
        cp16(d, g.Ah + goff);
        if (g.two_term) cp16(d + ARR_H * 2, g.Al + goff);
        cp16(d + 2 * ARR_H * 2, g.Wh + (size_t)(n0 + r) * D_ + k0 + c8);
    }
}

__global__ __launch_bounds__(256, 2) void gemm_f16_multi(
    GemmArgs ga0, GemmArgs ga1, GemmArgs ga2)
{
    extern __shared__ __half dsm[];
    const GemmArgs g = (blockIdx.z == 0) ? ga0 : ((blockIdx.z == 1) ? ga1 : ga2);

    const int t    = threadIdx.x;
    const int lane = t & 31;
    const int warp = t >> 5;
    const int wm   = warp >> 2;
    const int wn   = warp & 3;
    const int m0   = blockIdx.y * 128;
    const int n0   = blockIdx.x * 128;
    const uint32_t sb = smem_u32(dsm);

    float acc[4][4][4];
    #pragma unroll
    for (int i = 0; i < 4; i++)
        #pragma unroll
        for (int j = 0; j < 4; j++)
            #pragma unroll
            for (int r = 0; r < 4; r++) acc[i][j][r] = 0.0f;

    issue_chunk(g, m0, n0, 0, t, sb);
    cp_commit();
    issue_chunk(g, m0, n0, BKC, t, sb + STG_H * 2);
    cp_commit();

    for (int ck = 0; ck < NCH; ck++) {
        const int st = ck & 1;
        const __half* cah = dsm + st * STG_H;
        const __half* cal = cah + ARR_H;
        const __half* cbh = cah + 2 * ARR_H;

        if (ck + 1 < NCH) cp_wait<1>(); else cp_wait<0>();
        __syncthreads();

        #pragma unroll
        for (int ks = 0; ks < 2; ks++) {
            const int k0 = ks * 16;
            uint32_t bh[4][2];
            #pragma unroll
            for (int j = 0; j < 4; j++) {
                int row = wn * 32 + j * 8 + (lane & 7);
                int col = k0 + (((lane >> 3) & 1) << 3);
                ldsm_x2(bh[j][0], bh[j][1], smem_u32(cbh + row * SST + col));
            }
            #pragma unroll
            for (int i = 0; i < 4; i++) {
                int row = wm * 64 + i * 16 + (lane & 15);
                int col = k0 + ((lane >> 4) << 3);
                uint32_t ah0, ah1, ah2, ah3;
                ldsm_x4(ah0, ah1, ah2, ah3, smem_u32(cah + row * SST + col));
                #pragma unroll
                for (int j = 0; j < 4; j++)
                    mma_f16(acc[i][j], ah0, ah1, ah2, ah3, bh[j][0], bh[j][1]);
                if (g.two_term) {
                    uint32_t al0, al1, al2, al3;
                    ldsm_x4(al0, al1, al2, al3, smem_u32(cal + row * SST + col));
                    #pragma unroll
                    for (int j = 0; j < 4; j++)
                        mma_f16(acc[i][j], al0, al1, al2, al3, bh[j][0], bh[j][1]);
                }
            }
        }
        __syncthreads();

        if (ck + 2 < NCH) {
            issue_chunk(g, m0, n0, (ck + 2) * BKC, t, sb + st * STG_H * 2);
            cp_commit();
        }
    }

    const int lr = lane >> 2;
    const int lc = (lane & 3) << 1;
    #pragma unroll
    for (int i = 0; i < 4; i++) {
        #pragma unroll
        for (int j = 0; j < 4; j++) {
            int row = m0 + wm * 64 + i * 16 + lr;
            int col = n0 + wn * 32 + j * 8 + lc;
            float2 bz = *reinterpret_cast<const float2*>(g.bias + col);
            float v0 = (acc[i][j][0] + bz.x) * g.oscale;
            float v1 = (acc[i][j][1] + bz.y) * g.oscale;
            float v2 = (acc[i][j][2] + bz.x) * g.oscale;
            float v3 = (acc[i][j][3] + bz.y) * g.oscale;
            if (g.Chi) {
                if (g.Clo) {
                    __half h0, h1, h2, h3, l0, l1, l2, l3;
                    split2h(v0, h0, l0); split2h(v1, h1, l1);
                    split2h(v2, h2, l2); split2h(v3, h3, l3);
                    *reinterpret_cast<uint32_t*>(g.Chi + (size_t)row * D_ + col)       = pack_h(h0, h1);
                    *reinterpret_cast<uint32_t*>(g.Clo + (size_t)row * D_ + col)       = pack_h(l0, l1);
                    *reinterpret_cast<uint32_t*>(g.Chi + (size_t)(row + 8) * D_ + col) = pack_h(h2, h3);
                    *reinterpret_cast<uint32_t*>(g.Clo + (size_t)(row + 8) * D_ + col) = pack_h(l2, l3);
                } else {
                    *reinterpret_cast<uint32_t*>(g.Chi + (size_t)row * D_ + col) =
                        pack_h(__float2half_rn(v0), __float2half_rn(v1));
                    *reinterpret_cast<uint32_t*>(g.Chi + (size_t)(row + 8) * D_ + col) =
                        pack_h(__float2half_rn(v2), __float2half_rn(v3));
                }
            } else {
                float2 o0 = { v0, v1 }, o1 = { v2, v3 };
                *reinterpret_cast<float2*>(g.C + (size_t)row * D_ + col) = o0;
                *reinterpret_cast<float2*>(g.C + (size_t)(row + 8) * D_ + col) = o1;
            }
        }
    }
}

// ===========================================================================
// HMMA flash attention: Q/K/V/P/At single fp16; exp2-domain softmax.
// NEW: __launch_bounds__(256,2) to guarantee 2 CTAs/SM; K via ldsm_x4 pairs;
//      V via ldsm_x4.trans pairs (halves LDS-issue in the serial sections).
// ===========================================================================
#define FST 72

__global__ __launch_bounds__(256, 2) void flash_hmma_kernel(
    const __half* __restrict__ Qhi,
    const __half* __restrict__ Khi, const __half* __restrict__ Vhi,
    const int* __restrict__ mask,
    __half* __restrict__ Oh)
{
    __shared__ __align__(16) __half KH[2][64][FST];
    __shared__ __align__(16) __half VH[2][64][FST];
    __shared__ int MI[2][64];

    const int t    = threadIdx.x;
    const int lane = t & 31;
    const int warp = t >> 5;
    const int qt   = blockIdx.x;
    const int h    = blockIdx.y;
    const int b    = blockIdx.z;
    const int grow0 = b * L_ + qt * 128;
    const int ghc   = h * HD_;

    // ---- stage Q tile (128 rows, hi only) through KH[0]|VH[0] ----
    #pragma unroll
    for (int i = 0; i < 2; i++) {
        int v = t + i * 256;       // 0..511
        int r = v >> 2;            // 0..127
        int c = (v & 3) << 4;      // 0,16,32,48
        __half* dh = (r < 64) ? &KH[0][r][c] : &VH[0][r - 64][c];
        *reinterpret_cast<uint4*>(dh) =
            *reinterpret_cast<const uint4*>(Qhi + (size_t)(grow0 + r) * D_ + ghc + c);
        *reinterpret_cast<uint4*>(dh + 8) =
            *reinterpret_cast<const uint4*>(Qhi + (size_t)(grow0 + r) * D_ + ghc + c + 8);
    }
    __syncthreads();

    uint32_t qh[4][4];
    {
        int ar = warp * 16 + (lane & 15);
        int ac = (lane >> 4) << 3;
        const __half* sh = (ar < 64) ? &KH[0][ar][0] : &VH[0][ar - 64][0];
        #pragma unroll
        for (int kc = 0; kc < 4; kc++)
            ldsm_x4(qh[kc][0], qh[kc][1], qh[kc][2], qh[kc][3], smem_u32(sh + kc * 16 + ac));
    }
    __syncthreads();   // Q fragments read; smem stages free for K/V

    float O[8][4];
    #pragma unroll
    for (int j = 0; j < 8; j++)
        #pragma unroll
        for (int r = 0; r < 4; r++) O[j][r] = 0.0f;
    float m0 = -1e30f, m1 = -1e30f, l0 = 0.0f, l1 = 0.0f;

    auto issue_kv = [&](int tile, int st) {
        const int krow0 = b * L_ + tile * 64;
        #pragma unroll
        for (int i = 0; i < 2; i++) {
            int s = t + i * 256;
            int r = s >> 3;
            int c = (s & 7) << 3;
            size_t gb = (size_t)(krow0 + r) * D_ + ghc + c;
            cp16(smem_u32(&KH[st][r][c]), Khi + gb);
            cp16(smem_u32(&VH[st][r][c]), Vhi + gb);
        }
        if (t < 16) cp16(smem_u32(&MI[st][t * 4]), mask + b * L_ + tile * 64 + t * 4);
        cp_commit();
    };

    issue_kv(0, 0);
    issue_kv(1, 1);

    for (int kt = 0; kt < 16; kt++) {
        const int st = kt & 1;
        if (kt + 1 < 16) cp_wait<1>(); else cp_wait<0>();
        __syncthreads();

        // ---- S = Q K^T (single term); K fragments via x4 pairs ----
        float S[8][4];
        #pragma unroll
        for (int j = 0; j < 8; j++)
            S[j][0] = S[j][1] = S[j][2] = S[j][3] = 0.0f;
        #pragma unroll
        for (int jp = 0; jp < 4; jp++) {
            const int j0 = jp * 2;
            int brow = (j0 + (lane >> 4)) * 8 + (lane & 7);   // lanes 16-31: next n-group
            #pragma unroll
            for (int kc = 0; kc < 4; kc++) {
                int bcol = kc * 16 + (((lane >> 3) & 1) << 3);
                uint32_t b0, b1, b2, b3;
                ldsm_x4(b0, b1, b2, b3, smem_u32(&KH[st][brow][bcol]));
                mma_f16(S[j0],     qh[kc][0], qh[kc][1], qh[kc][2], qh[kc][3], b0, b1);
                mma_f16(S[j0 + 1], qh[kc][0], qh[kc][1], qh[kc][2], qh[kc][3], b2, b3);
            }
        }

        // ---- softmax in exp2 domain ----
        float rmax0 = -3.0e38f, rmax1 = -3.0e38f;
        #pragma unroll
        for (int j = 0; j < 8; j++) {
            int cidx = j * 8 + ((lane & 3) << 1);
            float ma = MI[st][cidx]     ? -1e30f : 0.0f;
            float mb = MI[st][cidx + 1] ? -1e30f : 0.0f;
            S[j][0] += ma; S[j][1] += mb; S[j][2] += ma; S[j][3] += mb;
            rmax0 = fmaxf(rmax0, fmaxf(S[j][0], S[j][1]));
            rmax1 = fmaxf(rmax1, fmaxf(S[j][2], S[j][3]));
        }
        rmax0 = fmaxf(rmax0, __shfl_xor_sync(0xffffffffu, rmax0, 1));
        rmax0 = fmaxf(rmax0, __shfl_xor_sync(0xffffffffu, rmax0, 2));
        rmax1 = fmaxf(rmax1, __shfl_xor_sync(0xffffffffu, rmax1, 1));
        rmax1 = fmaxf(rmax1, __shfl_xor_sync(0xffffffffu, rmax1, 2));

        float mn0 = fmaxf(m0, rmax0), mn1 = fmaxf(m1, rmax1);
        float a0 = exp2f(m0 - mn0), a1 = exp2f(m1 - mn1);
        m0 = mn0; m1 = mn1;

        float sum0 = 0.0f, sum1 = 0.0f;
        #pragma unroll
        for (int j = 0; j < 8; j++) {
            S[j][0] = exp2f(S[j][0] - mn0); sum0 += S[j][0];
            S[j][1] = exp2f(S[j][1] - mn0); sum0 += S[j][1];
            S[j][2] = exp2f(S[j][2] - mn1); sum1 += S[j][2];
            S[j][3] = exp2f(S[j][3] - mn1); sum1 += S[j][3];
        }
        sum0 += __shfl_xor_sync(0xffffffffu, sum0, 1);
        sum0 += __shfl_xor_sync(0xffffffffu, sum0, 2);
        sum1 += __shfl_xor_sync(0xffffffffu, sum1, 1);
        sum1 += __shfl_xor_sync(0xffffffffu, sum1, 2);
        l0 = l0 * a0 + sum0;
        l1 = l1 * a1 + sum1;

        #pragma unroll
        for (int j = 0; j < 8; j++) {
            O[j][0] *= a0; O[j][1] *= a0; O[j][2] *= a1; O[j][3] *= a1;
        }

        // ---- P -> single fp16 A-fragments ----
        uint32_t ph[4][4];
        #pragma unroll
        for (int kc = 0; kc < 4; kc++) {
            const float* x = S[2 * kc];
            const float* y = S[2 * kc + 1];
            ph[kc][0] = pack_h(__float2half_rn(x[0]), __float2half_rn(x[1]));
            ph[kc][1] = pack_h(__float2half_rn(x[2]), __float2half_rn(x[3]));
            ph[kc][2] = pack_h(__float2half_rn(y[0]), __float2half_rn(y[1]));
            ph[kc][3] = pack_h(__float2half_rn(y[2]), __float2half_rn(y[3]));
        }

        // ---- O += P V; V via ldmatrix.x4.trans pairs (two jn per load) ----
        #pragma unroll
        for (int jp = 0; jp < 4; jp++) {
            const int jn0 = jp * 2;
            #pragma unroll
            for (int kc = 0; kc < 4; kc++) {
                int vrow = kc * 16 + (lane & 15);
                int vcol = jn0 * 8 + ((lane >> 4) << 3);   // lanes 16-31: next jn
                uint32_t v0, v1, v2, v3;
                ldsm_x4t(v0, v1, v2, v3, smem_u32(&VH[st][vrow][vcol]));
                mma_f16(O[jn0],     ph[kc][0], ph[kc][1], ph[kc][2], ph[kc][3], v0, v1);
                mma_f16(O[jn0 + 1], ph[kc][0], ph[kc][1], ph[kc][2], ph[kc][3], v2, v3);
            }
        }
        __syncthreads();

        if (kt + 2 < 16) issue_kv(kt + 2, st);
    }

    // ---- normalize + write fp16 ----
    float inv0 = l0 > 0.0f ? 1.0f / l0 : 0.0f;
    float inv1 = l1 > 0.0f ? 1.0f / l1 : 0.0f;
    int row0 = grow0 + warp * 16 + (lane >> 2);
    int col  = ghc + ((lane & 3) << 1);
    #pragma unroll
    for (int jn = 0; jn < 8; jn++) {
        *reinterpret_cast<uint32_t*>(Oh + (size_t)row0 * D_ + col + jn * 8) =
            pack_h(__float2half_rn(O[jn][0] * inv0), __float2half_rn(O[jn][1] * inv0));
        *reinterpret_cast<uint32_t*>(Oh + (size_t)(row0 + 8) * D_ + col + jn * 8) =
            pack_h(__float2half_rn(O[jn][2] * inv1), __float2half_rn(O[jn][3] * inv1));
    }
}

// ---------------------------------------------------------------------------
// Launch
// ---------------------------------------------------------------------------
extern "C" void kernel_launch(void* const* d_in, const int* in_sizes, int n_in,
                              void* d_out, int out_size)
{
    const float* query = (const float*)d_in[0];
    const float* key   = (const float*)d_in[1];
    const float* value = (const float*)d_in[2];
    const int*   mask  = (const int*)d_in[3];
    const float* Wq = (const float*)d_in[4];
    const float* bq = (const float*)d_in[5];
    const float* Wk = (const float*)d_in[6];
    const float* bk = (const float*)d_in[7];
    const float* Wv = (const float*)d_in[8];
    const float* bv = (const float*)d_in[9];
    const float* Wo = (const float*)d_in[10];
    const float* bo = (const float*)d_in[11];
    float* out = (float*)d_out;

    void *p[12];
    cudaGetSymbolAddress(&p[0],  g_Iqh);  cudaGetSymbolAddress(&p[1],  g_Iql);
    cudaGetSymbolAddress(&p[2],  g_Ikh);  cudaGetSymbolAddress(&p[3],  g_Ivh);
    cudaGetSymbolAddress(&p[4],  g_Wq16); cudaGetSymbolAddress(&p[5],  g_Wk16);
    cudaGetSymbolAddress(&p[6],  g_Wv16); cudaGetSymbolAddress(&p[7],  g_Wo16);
    cudaGetSymbolAddress(&p[8],  g_Qhi);
    cudaGetSymbolAddress(&p[9],  g_Khi);  cudaGetSymbolAddress(&p[10], g_Vhi);
    cudaGetSymbolAddress(&p[11], g_Athi);
    __half* Iqh = (__half*)p[0];  __half* Iql = (__half*)p[1];
    __half* Ikh = (__half*)p[2];  __half* Ivh = (__half*)p[3];
    __half* Wq16 = (__half*)p[4]; __half* Wk16 = (__half*)p[5];
    __half* Wv16 = (__half*)p[6]; __half* Wo16 = (__half*)p[7];
    __half* Qhi = (__half*)p[8];
    __half* Khi = (__half*)p[9];  __half* Vhi = (__half*)p[10];
    __half* Athi = (__half*)p[11];

    cudaFuncSetAttribute(gemm_f16_multi,
                         cudaFuncAttributeMaxDynamicSharedMemorySize, GSMEM);

    prep_kernel<<<dim3(512, 1, 7), 256>>>(
        query, key, value, Wq, Wk, Wv, Wo,
        Iqh, Iql, Ikh, Ivh, Wq16, Wk16, Wv16, Wo16);

    // Q pre-scale folds 1/sqrt(HD) AND log2(e) for exp2-domain softmax
    GemmArgs qa = { Iqh, Iql, Wq16, bq, nullptr, Qhi, nullptr, 1, 0.125f * 1.44269504f };
    GemmArgs ka = { Ikh, nullptr, Wk16, bk, nullptr, Khi, nullptr, 0, 1.0f };
    GemmArgs va = { Ivh, nullptr, Wv16, bv, nullptr, Vhi, nullptr, 0, 1.0f };
    GemmArgs oa = { Athi, nullptr, Wo16, bo, out, nullptr, nullptr, 0, 1.0f };

    gemm_f16_multi<<<dim3(D_ / 128, M_TOT / 128, 3), 256, GSMEM>>>(qa, ka, va);

    flash_hmma_kernel<<<dim3(L_ / 128, H_, B_), 256>>>(
        Qhi, Khi, Vhi, mask, Athi);

    gemm_f16_multi<<<dim3(D_ / 128, M_TOT / 128, 1), 256, GSMEM>>>(oa, oa, oa);
}

// round 17
// speedup vs baseline: 1.6211x; 1.0678x over previous
#include <cuda_runtime.h>
#include <cuda_fp16.h>
#include <cstdint>

#define B_   4
#define L_   1024
#define D_   1024
#define H_   16
#define HD_  64
#define M_TOT (B_ * L_)   // 4096

// Scratch (static device globals — allocation-guard safe)
__device__ __half g_Iqh[M_TOT * D_];                      // query input (1-term now)
__device__ __half g_Ikh[M_TOT * D_];                      // key input (1-term)
__device__ __half g_Ivh[M_TOT * D_];                      // value input (1-term)
__device__ __half g_Wq16[D_ * D_], g_Wk16[D_ * D_], g_Wv16[D_ * D_], g_Wo16[D_ * D_];
__device__ __half g_Qhi[M_TOT * D_];                      // Q projected (fp16, pre-scaled 0.125*log2e)
__device__ __half g_Khi[M_TOT * D_], g_Vhi[M_TOT * D_];
__device__ __half g_Athi[M_TOT * D_];                     // attention out (fp16)

// ===========================================================================
// Helpers
// ===========================================================================
__device__ __forceinline__ uint32_t smem_u32(const void* p) {
    uint32_t a;
    asm("{ .reg .u64 t; cvta.to.shared.u64 t, %1; cvt.u32.u64 %0, t; }" : "=r"(a) : "l"(p));
    return a;
}
__device__ __forceinline__ void ldsm_x4(uint32_t& r0, uint32_t& r1, uint32_t& r2, uint32_t& r3, uint32_t a) {
    asm volatile("ldmatrix.sync.aligned.m8n8.x4.shared.b16 {%0,%1,%2,%3}, [%4];"
                 : "=r"(r0), "=r"(r1), "=r"(r2), "=r"(r3) : "r"(a));
}
__device__ __forceinline__ void ldsm_x2(uint32_t& r0, uint32_t& r1, uint32_t a) {
    asm volatile("ldmatrix.sync.aligned.m8n8.x2.shared.b16 {%0,%1}, [%2];"
                 : "=r"(r0), "=r"(r1) : "r"(a));
}
__device__ __forceinline__ void ldsm_x4t(uint32_t& r0, uint32_t& r1, uint32_t& r2, uint32_t& r3, uint32_t a) {
    asm volatile("ldmatrix.sync.aligned.m8n8.x4.trans.shared.b16 {%0,%1,%2,%3}, [%4];"
                 : "=r"(r0), "=r"(r1), "=r"(r2), "=r"(r3) : "r"(a));
}
__device__ __forceinline__ void mma_f16(float* c,
    uint32_t a0, uint32_t a1, uint32_t a2, uint32_t a3, uint32_t b0, uint32_t b1) {
    asm volatile("mma.sync.aligned.m16n8k16.row.col.f32.f16.f16.f32 "
                 "{%0,%1,%2,%3}, {%4,%5,%6,%7}, {%8,%9}, {%0,%1,%2,%3};"
                 : "+f"(c[0]), "+f"(c[1]), "+f"(c[2]), "+f"(c[3])
                 : "r"(a0), "r"(a1), "r"(a2), "r"(a3), "r"(b0), "r"(b1));
}
__device__ __forceinline__ uint32_t pack_h(__half lo, __half hi) {
    return ((uint32_t)__half_as_ushort(hi) << 16) | __half_as_ushort(lo);
}
__device__ __forceinline__ void split2h(float x, __half& h, __half& l) {
    h = __float2half_rn(x);
    l = __float2half_rn(x - __half2float(h));
}
__device__ __forceinline__ void cp16(uint32_t dst, const void* src) {
    asm volatile("cp.async.cg.shared.global [%0], [%1], 16;" :: "r"(dst), "l"(src));
}
__device__ __forceinline__ void cp_commit() { asm volatile("cp.async.commit_group;"); }
template<int N> __device__ __forceinline__ void cp_wait() {
    asm volatile("cp.async.wait_group %0;" :: "n"(N));
}

// ===========================================================================
// Prep: all inputs + weights -> single fp16.  grid (512,1,7)
// ===========================================================================
__global__ __launch_bounds__(256) void prep_kernel(
    const float* __restrict__ q, const float* __restrict__ k, const float* __restrict__ v,
    const float* __restrict__ wq, const float* __restrict__ wk,
    const float* __restrict__ wv, const float* __restrict__ wo,
    __half* qh, __half* kh, __half* vh,
    __half* wqh, __half* wkh, __half* wvh, __half* woh)
{
    const int z = blockIdx.z;
    const int base = blockIdx.x * 256 + threadIdx.x;
    if (z < 3) {
        const float* src = (z == 0) ? q : (z == 1) ? k : v;
        __half* dst = (z == 0) ? qh : (z == 1) ? kh : vh;
        #pragma unroll
        for (int i = 0; i < 8; i++) {
            int e4 = base + i * 131072;
            float4 x = reinterpret_cast<const float4*>(src)[e4];
            uint2 hv = { pack_h(__float2half_rn(x.x), __float2half_rn(x.y)),
                         pack_h(__float2half_rn(x.z), __float2half_rn(x.w)) };
            *reinterpret_cast<uint2*>(dst + (size_t)e4 * 4) = hv;
        }
    } else {
        const float* src = (z == 3) ? wq : (z == 4) ? wk : (z == 5) ? wv : wo;
        __half* dst = (z == 3) ? wqh : (z == 4) ? wkh : (z == 5) ? wvh : woh;
        #pragma unroll
        for (int i = 0; i < 2; i++) {
            int e4 = base + i * 131072;
            float4 x = reinterpret_cast<const float4*>(src)[e4];
            uint2 wv2 = { pack_h(__float2half_rn(x.x), __float2half_rn(x.y)),
                          pack_h(__float2half_rn(x.z), __float2half_rn(x.w)) };
            *reinterpret_cast<uint2*>(dst + (size_t)e4 * 4) = wv2;
        }
    }
}

// ===========================================================================
// fp16 HMMA GEMM, cp.async double-buffered (R13/R15 proven structure — UNCHANGED).
//   C = (Ah [+ Al]) @ Wh^T + bias, then * oscale.
// ===========================================================================
#define BKC   32
#define NCH   (D_ / BKC)   // 32
#define SST   40
#define ARR_H (128 * SST)
#define STG_H (3 * ARR_H)
#define GSMEM (2 * STG_H * 2)          // 61440 bytes

struct GemmArgs {
    const __half* Ah;
    const __half* Al;
    const __half* Wh;
    const float*  bias;
    float*  C;
    __half* Chi;
    __half* Clo;
    int     two_term;   // A-side lo term present
    float   oscale;     // output scale (applied after bias)
};

__device__ __forceinline__ void issue_chunk(
    const GemmArgs& g, int m0, int n0, int k0, int t, uint32_t stage_b)
{
    #pragma unroll
    for (int i = 0; i < 2; i++) {
        int s  = t + (i << 8);
        int r  = s >> 2;
        int c8 = (s & 3) << 3;
        uint32_t d = stage_b + (uint32_t)(r * SST + c8) * 2;
        size_t goff = (size_t)(m0 + r) * D_ + k0 + c8;
        cp16(d, g.Ah + goff);
        if (g.two_term) cp16(d + ARR_H * 2, g.Al + goff);
        cp16(d + 2 * ARR_H * 2, g.Wh + (size_t)(n0 + r) * D_ + k0 + c8);
    }
}

__global__ __launch_bounds__(256, 2) void gemm_f16_multi(
    GemmArgs ga0, GemmArgs ga1, GemmArgs ga2)
{
    extern __shared__ __half dsm[];
    const GemmArgs g = (blockIdx.z == 0) ? ga0 : ((blockIdx.z == 1) ? ga1 : ga2);

    const int t    = threadIdx.x;
    const int lane = t & 31;
    const int warp = t >> 5;
    const int wm   = warp >> 2;
    const int wn   = warp & 3;
    const int m0   = blockIdx.y * 128;
    const int n0   = blockIdx.x * 128;
    const uint32_t sb = smem_u32(dsm);

    float acc[4][4][4];
    #pragma unroll
    for (int i = 0; i < 4; i++)
        #pragma unroll
        for (int j = 0; j < 4; j++)
            #pragma unroll
            for (int r = 0; r < 4; r++) acc[i][j][r] = 0.0f;

    issue_chunk(g, m0, n0, 0, t, sb);
    cp_commit();
    issue_chunk(g, m0, n0, BKC, t, sb + STG_H * 2);
    cp_commit();

    for (int ck = 0; ck < NCH; ck++) {
        const int st = ck & 1;
        const __half* cah = dsm + st * STG_H;
        const __half* cal = cah + ARR_H;
        const __half* cbh = cah + 2 * ARR_H;

        if (ck + 1 < NCH) cp_wait<1>(); else cp_wait<0>();
        __syncthreads();

        #pragma unroll
        for (int ks = 0; ks < 2; ks++) {
            const int k0 = ks * 16;
            uint32_t bh[4][2];
            #pragma unroll
            for (int j = 0; j < 4; j++) {
                int row = wn * 32 + j * 8 + (lane & 7);
                int col = k0 + (((lane >> 3) & 1) << 3);
                ldsm_x2(bh[j][0], bh[j][1], smem_u32(cbh + row * SST + col));
            }
            #pragma unroll
            for (int i = 0; i < 4; i++) {
                int row = wm * 64 + i * 16 + (lane & 15);
                int col = k0 + ((lane >> 4) << 3);
                uint32_t ah0, ah1, ah2, ah3;
                ldsm_x4(ah0, ah1, ah2, ah3, smem_u32(cah + row * SST + col));
                #pragma unroll
                for (int j = 0; j < 4; j++)
                    mma_f16(acc[i][j], ah0, ah1, ah2, ah3, bh[j][0], bh[j][1]);
                if (g.two_term) {
                    uint32_t al0, al1, al2, al3;
                    ldsm_x4(al0, al1, al2, al3, smem_u32(cal + row * SST + col));
                    #pragma unroll
                    for (int j = 0; j < 4; j++)
                        mma_f16(acc[i][j], al0, al1, al2, al3, bh[j][0], bh[j][1]);
                }
            }
        }
        __syncthreads();

        if (ck + 2 < NCH) {
            issue_chunk(g, m0, n0, (ck + 2) * BKC, t, sb + st * STG_H * 2);
            cp_commit();
        }
    }

    const int lr = lane >> 2;
    const int lc = (lane & 3) << 1;
    #pragma unroll
    for (int i = 0; i < 4; i++) {
        #pragma unroll
        for (int j = 0; j < 4; j++) {
            int row = m0 + wm * 64 + i * 16 + lr;
            int col = n0 + wn * 32 + j * 8 + lc;
            float2 bz = *reinterpret_cast<const float2*>(g.bias + col);
            float v0 = (acc[i][j][0] + bz.x) * g.oscale;
            float v1 = (acc[i][j][1] + bz.y) * g.oscale;
            float v2 = (acc[i][j][2] + bz.x) * g.oscale;
            float v3 = (acc[i][j][3] + bz.y) * g.oscale;
            if (g.Chi) {
                if (g.Clo) {
                    __half h0, h1, h2, h3, l0, l1, l2, l3;
                    split2h(v0, h0, l0); split2h(v1, h1, l1);
                    split2h(v2, h2, l2); split2h(v3, h3, l3);
                    *reinterpret_cast<uint32_t*>(g.Chi + (size_t)row * D_ + col)       = pack_h(h0, h1);
                    *reinterpret_cast<uint32_t*>(g.Clo + (size_t)row * D_ + col)       = pack_h(l0, l1);
                    *reinterpret_cast<uint32_t*>(g.Chi + (size_t)(row + 8) * D_ + col) = pack_h(h2, h3);
                    *reinterpret_cast<uint32_t*>(g.Clo + (size_t)(row + 8) * D_ + col) = pack_h(l2, l3);
                } else {
                    *reinterpret_cast<uint32_t*>(g.Chi + (size_t)row * D_ + col) =
                        pack_h(__float2half_rn(v0), __float2half_rn(v1));
                    *reinterpret_cast<uint32_t*>(g.Chi + (size_t)(row + 8) * D_ + col) =
                        pack_h(__float2half_rn(v2), __float2half_rn(v3));
                }
            } else {
                float2 o0 = { v0, v1 }, o1 = { v2, v3 };
                *reinterpret_cast<float2*>(g.C + (size_t)row * D_ + col) = o0;
                *reinterpret_cast<float2*>(g.C + (size_t)(row + 8) * D_ + col) = o1;
            }
        }
    }
}

// ===========================================================================
// HMMA flash attention (R16 structure — UNCHANGED): single fp16 everywhere,
// exp2-domain softmax, K via x4 pairs, V via x4.trans pairs.
// ===========================================================================
#define FST 72

__global__ __launch_bounds__(256, 2) void flash_hmma_kernel(
    const __half* __restrict__ Qhi,
    const __half* __restrict__ Khi, const __half* __restrict__ Vhi,
    const int* __restrict__ mask,
    __half* __restrict__ Oh)
{
    __shared__ __align__(16) __half KH[2][64][FST];
    __shared__ __align__(16) __half VH[2][64][FST];
    __shared__ int MI[2][64];

    const int t    = threadIdx.x;
    const int lane = t & 31;
    const int warp = t >> 5;
    const int qt   = blockIdx.x;
    const int h    = blockIdx.y;
    const int b    = blockIdx.z;
    const int grow0 = b * L_ + qt * 128;
    const int ghc   = h * HD_;

    // ---- stage Q tile (128 rows, hi only) through KH[0]|VH[0] ----
    #pragma unroll
    for (int i = 0; i < 2; i++) {
        int v = t + i * 256;       // 0..511
        int r = v >> 2;            // 0..127
        int c = (v & 3) << 4;      // 0,16,32,48
        __half* dh = (r < 64) ? &KH[0][r][c] : &VH[0][r - 64][c];
        *reinterpret_cast<uint4*>(dh) =
            *reinterpret_cast<const uint4*>(Qhi + (size_t)(grow0 + r) * D_ + ghc + c);
        *reinterpret_cast<uint4*>(dh + 8) =
            *reinterpret_cast<const uint4*>(Qhi + (size_t)(grow0 + r) * D_ + ghc + c + 8);
    }
    __syncthreads();

    uint32_t qh[4][4];
    {
        int ar = warp * 16 + (lane & 15);
        int ac = (lane >> 4) << 3;
        const __half* sh = (ar < 64) ? &KH[0][ar][0] : &VH[0][ar - 64][0];
        #pragma unroll
        for (int kc = 0; kc < 4; kc++)
            ldsm_x4(qh[kc][0], qh[kc][1], qh[kc][2], qh[kc][3], smem_u32(sh + kc * 16 + ac));
    }
    __syncthreads();   // Q fragments read; smem stages free for K/V

    float O[8][4];
    #pragma unroll
    for (int j = 0; j < 8; j++)
        #pragma unroll
        for (int r = 0; r < 4; r++) O[j][r] = 0.0f;
    float m0 = -1e30f, m1 = -1e30f, l0 = 0.0f, l1 = 0.0f;

    auto issue_kv = [&](int tile, int st) {
        const int krow0 = b * L_ + tile * 64;
        #pragma unroll
        for (int i = 0; i < 2; i++) {
            int s = t + i * 256;
            int r = s >> 3;
            int c = (s & 7) << 3;
            size_t gb = (size_t)(krow0 + r) * D_ + ghc + c;
            cp16(smem_u32(&KH[st][r][c]), Khi + gb);
            cp16(smem_u32(&VH[st][r][c]), Vhi + gb);
        }
        if (t < 16) cp16(smem_u32(&MI[st][t * 4]), mask + b * L_ + tile * 64 + t * 4);
        cp_commit();
    };

    issue_kv(0, 0);
    issue_kv(1, 1);

    for (int kt = 0; kt < 16; kt++) {
        const int st = kt & 1;
        if (kt + 1 < 16) cp_wait<1>(); else cp_wait<0>();
        __syncthreads();

        // ---- S = Q K^T (single term); K fragments via x4 pairs ----
        float S[8][4];
        #pragma unroll
        for (int j = 0; j < 8; j++)
            S[j][0] = S[j][1] = S[j][2] = S[j][3] = 0.0f;
        #pragma unroll
        for (int jp = 0; jp < 4; jp++) {
            const int j0 = jp * 2;
            int brow = (j0 + (lane >> 4)) * 8 + (lane & 7);   // lanes 16-31: next n-group
            #pragma unroll
            for (int kc = 0; kc < 4; kc++) {
                int bcol = kc * 16 + (((lane >> 3) & 1) << 3);
                uint32_t b0, b1, b2, b3;
                ldsm_x4(b0, b1, b2, b3, smem_u32(&KH[st][brow][bcol]));
                mma_f16(S[j0],     qh[kc][0], qh[kc][1], qh[kc][2], qh[kc][3], b0, b1);
                mma_f16(S[j0 + 1], qh[kc][0], qh[kc][1], qh[kc][2], qh[kc][3], b2, b3);
            }
        }

        // ---- softmax in exp2 domain ----
        float rmax0 = -3.0e38f, rmax1 = -3.0e38f;
        #pragma unroll
        for (int j = 0; j < 8; j++) {
            int cidx = j * 8 + ((lane & 3) << 1);
            float ma = MI[st][cidx]     ? -1e30f : 0.0f;
            float mb = MI[st][cidx + 1] ? -1e30f : 0.0f;
            S[j][0] += ma; S[j][1] += mb; S[j][2] += ma; S[j][3] += mb;
            rmax0 = fmaxf(rmax0, fmaxf(S[j][0], S[j][1]));
            rmax1 = fmaxf(rmax1, fmaxf(S[j][2], S[j][3]));
        }
        rmax0 = fmaxf(rmax0, __shfl_xor_sync(0xffffffffu, rmax0, 1));
        rmax0 = fmaxf(rmax0, __shfl_xor_sync(0xffffffffu, rmax0, 2));
        rmax1 = fmaxf(rmax1, __shfl_xor_sync(0xffffffffu, rmax1, 1));
        rmax1 = fmaxf(rmax1, __shfl_xor_sync(0xffffffffu, rmax1, 2));

        float mn0 = fmaxf(m0, rmax0), mn1 = fmaxf(m1, rmax1);
        float a0 = exp2f(m0 - mn0), a1 = exp2f(m1 - mn1);
        m0 = mn0; m1 = mn1;

        float sum0 = 0.0f, sum1 = 0.0f;
        #pragma unroll
        for (int j = 0; j < 8; j++) {
            S[j][0] = exp2f(S[j][0] - mn0); sum0 += S[j][0];
            S[j][1] = exp2f(S[j][1] - mn0); sum0 += S[j][1];
            S[j][2] = exp2f(S[j][2] - mn1); sum1 += S[j][2];
            S[j][3] = exp2f(S[j][3] - mn1); sum1 += S[j][3];
        }
        sum0 += __shfl_xor_sync(0xffffffffu, sum0, 1);
        sum0 += __shfl_xor_sync(0xffffffffu, sum0, 2);
        sum1 += __shfl_xor_sync(0xffffffffu, sum1, 1);
        sum1 += __shfl_xor_sync(0xffffffffu, sum1, 2);
        l0 = l0 * a0 + sum0;
        l1 = l1 * a1 + sum1;

        #pragma unroll
        for (int j = 0; j < 8; j++) {
            O[j][0] *= a0; O[j][1] *= a0; O[j][2] *= a1; O[j][3] *= a1;
        }

        // ---- P -> single fp16 A-fragments ----
        uint32_t ph[4][4];
        #pragma unroll
        for (int kc = 0; kc < 4; kc++) {
            const float* x = S[2 * kc];
            const float* y = S[2 * kc + 1];
            ph[kc][0] = pack_h(__float2half_rn(x[0]), __float2half_rn(x[1]));
            ph[kc][1] = pack_h(__float2half_rn(x[2]), __float2half_rn(x[3]));
            ph[kc][2] = pack_h(__float2half_rn(y[0]), __float2half_rn(y[1]));
            ph[kc][3] = pack_h(__float2half_rn(y[2]), __float2half_rn(y[3]));
        }

        // ---- O += P V; V via ldmatrix.x4.trans pairs (two jn per load) ----
        #pragma unroll
        for (int jp = 0; jp < 4; jp++) {
            const int jn0 = jp * 2;
            #pragma unroll
            for (int kc = 0; kc < 4; kc++) {
                int vrow = kc * 16 + (lane & 15);
                int vcol = jn0 * 8 + ((lane >> 4) << 3);   // lanes 16-31: next jn
                uint32_t v0, v1, v2, v3;
                ldsm_x4t(v0, v1, v2, v3, smem_u32(&VH[st][vrow][vcol]));
                mma_f16(O[jn0],     ph[kc][0], ph[kc][1], ph[kc][2], ph[kc][3], v0, v1);
                mma_f16(O[jn0 + 1], ph[kc][0], ph[kc][1], ph[kc][2], ph[kc][3], v2, v3);
            }
        }
        __syncthreads();

        if (kt + 2 < 16) issue_kv(kt + 2, st);
    }

    // ---- normalize + write fp16 ----
    float inv0 = l0 > 0.0f ? 1.0f / l0 : 0.0f;
    float inv1 = l1 > 0.0f ? 1.0f / l1 : 0.0f;
    int row0 = grow0 + warp * 16 + (lane >> 2);
    int col  = ghc + ((lane & 3) << 1);
    #pragma unroll
    for (int jn = 0; jn < 8; jn++) {
        *reinterpret_cast<uint32_t*>(Oh + (size_t)row0 * D_ + col + jn * 8) =
            pack_h(__float2half_rn(O[jn][0] * inv0), __float2half_rn(O[jn][1] * inv0));
        *reinterpret_cast<uint32_t*>(Oh + (size_t)(row0 + 8) * D_ + col + jn * 8) =
            pack_h(__float2half_rn(O[jn][2] * inv1), __float2half_rn(O[jn][3] * inv1));
    }
}

// ---------------------------------------------------------------------------
// Launch
// ---------------------------------------------------------------------------
extern "C" void kernel_launch(void* const* d_in, const int* in_sizes, int n_in,
                              void* d_out, int out_size)
{
    const float* query = (const float*)d_in[0];
    const float* key   = (const float*)d_in[1];
    const float* value = (const float*)d_in[2];
    const int*   mask  = (const int*)d_in[3];
    const float* Wq = (const float*)d_in[4];
    const float* bq = (const float*)d_in[5];
    const float* Wk = (const float*)d_in[6];
    const float* bk = (const float*)d_in[7];
    const float* Wv = (const float*)d_in[8];
    const float* bv = (const float*)d_in[9];
    const float* Wo = (const float*)d_in[10];
    const float* bo = (const float*)d_in[11];
    float* out = (float*)d_out;

    void *p[11];
    cudaGetSymbolAddress(&p[0],  g_Iqh);
    cudaGetSymbolAddress(&p[1],  g_Ikh);  cudaGetSymbolAddress(&p[2],  g_Ivh);
    cudaGetSymbolAddress(&p[3],  g_Wq16); cudaGetSymbolAddress(&p[4],  g_Wk16);
    cudaGetSymbolAddress(&p[5],  g_Wv16); cudaGetSymbolAddress(&p[6],  g_Wo16);
    cudaGetSymbolAddress(&p[7],  g_Qhi);
    cudaGetSymbolAddress(&p[8],  g_Khi);  cudaGetSymbolAddress(&p[9],  g_Vhi);
    cudaGetSymbolAddress(&p[10], g_Athi);
    __half* Iqh = (__half*)p[0];
    __half* Ikh = (__half*)p[1];  __half* Ivh = (__half*)p[2];
    __half* Wq16 = (__half*)p[3]; __half* Wk16 = (__half*)p[4];
    __half* Wv16 = (__half*)p[5]; __half* Wo16 = (__half*)p[6];
    __half* Qhi = (__half*)p[7];
    __half* Khi = (__half*)p[8];  __half* Vhi = (__half*)p[9];
    __half* Athi = (__half*)p[10];

    cudaFuncSetAttribute(gemm_f16_multi,
                         cudaFuncAttributeMaxDynamicSharedMemorySize, GSMEM);

    prep_kernel<<<dim3(512, 1, 7), 256>>>(
        query, key, value, Wq, Wk, Wv, Wo,
        Iqh, Ikh, Ivh, Wq16, Wk16, Wv16, Wo16);

    // Q pre-scale folds 1/sqrt(HD) AND log2(e) for exp2-domain softmax
    GemmArgs qa = { Iqh, nullptr, Wq16, bq, nullptr, Qhi, nullptr, 0, 0.125f * 1.44269504f };
    GemmArgs ka = { Ikh, nullptr, Wk16, bk, nullptr, Khi, nullptr, 0, 1.0f };
    GemmArgs va = { Ivh, nullptr, Wv16, bv, nullptr, Vhi, nullptr, 0, 1.0f };
    GemmArgs oa = { Athi, nullptr, Wo16, bo, out, nullptr, nullptr, 0, 1.0f };

    gemm_f16_multi<<<dim3(D_ / 128, M_TOT / 128, 3), 256, GSMEM>>>(qa, ka, va);

    flash_hmma_kernel<<<dim3(L_ / 128, H_, B_), 256>>>(
        Qhi, Khi, Vhi, mask, Athi);

    gemm_f16_multi<<<dim3(D_ / 128, M_TOT / 128, 1), 256, GSMEM>>>(oa, oa, oa);
}